// round 12
// baseline (speedup 1.0000x reference)
#include <cuda_runtime.h>
#include <cuda_fp16.h>
#include <math.h>
#include <stdint.h>

// ---------------- problem constants ----------------
#define NB    4
#define NC    32
#define NSP   1024
#define ND    1024
#define NBH   16
#define SCALE 0.17677669529663687f   // 1/sqrt(32)
#define EPSGN 1e-5f

// ---------------- scratch (device globals; allocation-free) ----------------
__device__ float g_Q  [NBH * ND * NSP];       // q natural [bh][d][n] fp32 (pre-softmax)
__device__ float g_K  [NBH * ND * NSP];       // k natural [bh][d][n] fp32 (pre-softmax)
__device__ float g_X  [NBH * ND * NSP];       // attention out [bh][e][n] fp32
__device__ float g_Y  [NB * NC * NSP];        // projection out, pre-GN
__device__ float g_stats[8];                  // mean[4], var[4]
__device__ float g_qinv[NBH * NSP];           // 256 / sum(exp(q)) per (z,n)

// f16 operand arrays, TILE-PACKED + PRE-SWIZZLED:
// layout: [z][tile(8)][kchunk(32)] blocks of 8192B; block = 128 rows x 64B,
// element (r, kk): byte r*64 + (((kk>>3)+(r>>1))&3)*16 + (kk&7)*2
#define HFN (NBH * ND * NSP / 8)
__device__ uint4 g_Vf4[HFN];   // v  [e][n]             f16
__device__ uint4 g_Kf4[HFN];   // 256*k-softmax [d][n]  f16
__device__ uint4 g_Qf4[HFN];   // 256*q-softmax^T [n][d] f16
__device__ uint4 g_Cf4[HFN];   // ctx^T [e][d]          f16

// ---------------- small helpers ----------------
__device__ __forceinline__ uint32_t smem_u32(const void* p) {
    uint32_t a;
    asm("{ .reg .u64 t; cvta.to.shared.u64 t, %1; cvt.u32.u64 %0, t; }" : "=r"(a) : "l"(p));
    return a;
}
__device__ __forceinline__ unsigned packh2(float a, float b) {
    __half2 p = __floats2half2_rn(a, b);
    return *reinterpret_cast<unsigned*>(&p);
}
// byte offset of element (row, k) of matrix z in packed-swizzled layout
__device__ __forceinline__ size_t pkoff(int z, int row, int k) {
    size_t blk = (size_t)(z * 8 + (row >> 7)) * 32 + (k >> 5);
    int r = row & 127, kk = k & 31;
    return blk * 8192 +
           (uint32_t)(r * 64 + ((((kk >> 3) + (r >> 1)) & 3) << 4) + (kk & 7) * 2);
}
// in-smem 16B-chunk address within an 8KB region (same swizzle)
__device__ __forceinline__ uint32_t swzoff(int R, int ch) {
    return (uint32_t)(R * 64 + (((ch + (R >> 1)) & 3) << 4));
}
__device__ __forceinline__ void mbar_init(uint32_t a, uint32_t cnt) {
    asm volatile("mbarrier.init.shared.b64 [%0], %1;" :: "r"(a), "r"(cnt) : "memory");
}
__device__ __forceinline__ void mbar_expect_tx(uint32_t a, uint32_t tx) {
    asm volatile("mbarrier.arrive.expect_tx.shared.b64 _, [%0], %1;"
                 :: "r"(a), "r"(tx) : "memory");
}
__device__ __forceinline__ void mbar_wait(uint32_t a, uint32_t phase) {
    asm volatile(
        "{\n\t.reg .pred P;\n"
        "W%=:\n\t"
        "mbarrier.try_wait.parity.shared::cta.b64 P, [%0], %1;\n\t"
        "@!P bra W%=;\n\t}"
        :: "r"(a), "r"(phase) : "memory");
}
__device__ __forceinline__ void bulkcp(uint32_t sdst, const void* gsrc,
                                       uint32_t bytes, uint32_t mb) {
    asm volatile(
        "cp.async.bulk.shared::cta.global.mbarrier::complete_tx::bytes [%0], [%1], %2, [%3];"
        :: "r"(sdst), "l"(gsrc), "r"(bytes), "r"(mb) : "memory");
}
__device__ __forceinline__ void ldsm4(unsigned* r, uint32_t addr) {
    asm volatile("ldmatrix.sync.aligned.m8n8.x4.shared.b16 {%0,%1,%2,%3}, [%4];"
                 : "=r"(r[0]), "=r"(r[1]), "=r"(r[2]), "=r"(r[3]) : "r"(addr));
}
__device__ __forceinline__ void mma16816(float* c, const unsigned* a, const unsigned* b) {
    asm volatile(
        "mma.sync.aligned.m16n8k16.row.col.f32.f16.f16.f32 "
        "{%0,%1,%2,%3}, {%4,%5,%6,%7}, {%8,%9}, {%0,%1,%2,%3};"
        : "+f"(c[0]), "+f"(c[1]), "+f"(c[2]), "+f"(c[3])
        : "r"(a[0]), "r"(a[1]), "r"(a[2]), "r"(a[3]), "r"(b[0]), "r"(b[1]));
}

// ============================================================
// Kernel 1: QKV projection. q,k -> fp32 natural; v -> f16 packed.
// ============================================================
__global__ __launch_bounds__(256) void qkv_kernel(const float* __restrict__ img,
                                                  const float* __restrict__ w,
                                                  const float* __restrict__ bias) {
    __shared__ float xs[32][128];
    __shared__ float ws[64][32];
    __shared__ float bs[64];

    const int b  = blockIdx.z;
    const int o0 = blockIdx.y * 64;
    const int n0 = blockIdx.x * 128;
    const int t  = threadIdx.x;

#pragma unroll
    for (int i = 0; i < 4; i++) {
        int idx = t + 256 * i;
        int c = idx >> 5, c4 = (idx & 31) << 2;
        *(float4*)&xs[c][c4] = *(const float4*)&img[((size_t)b * 32 + c) * 1024 + n0 + c4];
    }
#pragma unroll
    for (int i = 0; i < 2; i++) {
        int idx = t + 256 * i;
        int o = idx >> 3, c4 = (idx & 7) << 2;
        *(float4*)&ws[o][c4] = *(const float4*)&w[(size_t)(o0 + o) * 32 + c4];
    }
    if (t < 64) bs[t] = bias[o0 + t];
    __syncthreads();

    const int tx = t & 31;
    const int oy = t >> 5;

    float acc[8][4];
#pragma unroll
    for (int r = 0; r < 8; r++) {
        float bv = bs[8 * oy + r];
#pragma unroll
        for (int i = 0; i < 4; i++) acc[r][i] = bv;
    }
#pragma unroll
    for (int c = 0; c < 32; c++) {
        float4 x = *(const float4*)&xs[c][4 * tx];
#pragma unroll
        for (int r = 0; r < 8; r++) {
            float wv = ws[8 * oy + r][c];
            acc[r][0] += wv * x.x; acc[r][1] += wv * x.y;
            acc[r][2] += wv * x.z; acc[r][3] += wv * x.w;
        }
    }

    const int nglob = n0 + 4 * tx;
#pragma unroll
    for (int r = 0; r < 8; r++) {
        int o     = o0 + 8 * oy + r;
        int which = o >> 12;
        int oc    = o & 4095;
        int h     = oc & 3;
        int cch   = oc >> 2;
        int zz    = b * 4 + h;
        if (which == 2) {
            uint2 hv;
            hv.x = packh2(acc[r][0], acc[r][1]);
            hv.y = packh2(acc[r][2], acc[r][3]);
            *(uint2*)((char*)g_Vf4 + pkoff(zz, cch, nglob)) = hv;   // 8B aligned (nglob%4==0)
        } else {
            float* dst = (which == 0) ? g_Q : g_K;
            *(float4*)&dst[((size_t)zz << 20) + (size_t)cch * 1024 + nglob] =
                make_float4(acc[r][0], acc[r][1], acc[r][2], acc[r][3]);
        }
    }
}

// ============================================================
// Kernel 2 (fused dual-role): blockIdx.z==0 -> k softmax (x256, f16 packed);
// blockIdx.z==1 -> q denominator g_qinv[z][n] = 256 / sum_d exp(q[d][n]).
// grid (32, 16, 2), block 1024.  (Fusion keeps gemm0 at launch #4 for ncu.)
// ============================================================
__global__ __launch_bounds__(1024) void ksm_qsum_kernel() {
    const int z = blockIdx.y;
    if (blockIdx.z == 0) {
        const int lane = threadIdx.x & 31;
        const int w    = threadIdx.x >> 5;
        const int d    = blockIdx.x * 32 + w;
        const float* src = g_K + ((size_t)z << 20) + (size_t)d * 1024;

        float vals[32];
        float m = -3.402823466e38f;
#pragma unroll
        for (int j = 0; j < 32; j++) {
            vals[j] = src[j * 32 + lane];
            m = fmaxf(m, vals[j]);
        }
#pragma unroll
        for (int o = 16; o; o >>= 1) m = fmaxf(m, __shfl_xor_sync(0xffffffffu, m, o));
        float s = 0.f;
#pragma unroll
        for (int j = 0; j < 32; j++) { vals[j] = expf(vals[j] - m); s += vals[j]; }
#pragma unroll
        for (int o = 16; o; o >>= 1) s += __shfl_xor_sync(0xffffffffu, s, o);
        float inv = 256.f / s;

        char* KfB = (char*)g_Kf4;
#pragma unroll
        for (int j = 0; j < 32; j++)
            *(__half*)(KfB + pkoff(z, d, j * 32 + lane)) = __float2half_rn(vals[j] * inv);
    } else {
        __shared__ float red[32][32];
        const int nl = threadIdx.x & 31;
        const int dg = threadIdx.x >> 5;
        const int n  = blockIdx.x * 32 + nl;
        const float* src = g_Q + ((size_t)z << 20) + n;

        float s = 0.f;
#pragma unroll 8
        for (int d = dg * 32; d < dg * 32 + 32; d++) s += expf(src[(size_t)d * 1024]);
        red[dg][nl] = s;
        __syncthreads();
        if (dg == 0) {
            float tot = 0.f;
#pragma unroll
            for (int r = 0; r < 32; r++) tot += red[r][nl];
            g_qinv[z * 1024 + n] = 256.f / tot;
        }
    }
}

// ============================================================
// Kernel 3: q softmax-apply (x256) + transpose -> f16 packed qT[n][d].
// ============================================================
__global__ void q_t_kernel() {
    __shared__ float s[32][33];
    const int z  = blockIdx.z;
    const int d0 = blockIdx.y * 32;
    const int n0 = blockIdx.x * 32;
    const int tx = threadIdx.x, ty = threadIdx.y;
    const float* src = g_Q + ((size_t)z << 20);
    const float inv = g_qinv[z * 1024 + n0 + tx];

#pragma unroll
    for (int i = 0; i < 4; i++) {
        int r = ty + 8 * i;
        s[r][tx] = expf(src[(size_t)(d0 + r) * 1024 + n0 + tx]) * inv;
    }
    __syncthreads();

    char* QfB = (char*)g_Qf4;
#pragma unroll
    for (int i = 0; i < 4; i++) {
        int nl = ty + 8 * i;
        *(__half*)(QfB + pkoff(z, n0 + nl, d0 + tx)) = __float2half_rn(s[tx][nl]);
    }
}

// ============================================================
// Kernel 4: single-pass f16 TN GEMM, bulk-TMA loads + mma.sync.
//   D[m,n'] = sum_k A[m,k]*B[n',k]
// stage 0: A=Vf, B=Kf (256x) -> Cf packed, scale 1/256
// stage 1: A=Cf, B=Qf (256x) -> X [e][n] fp32, scale SCALE/256
// CTA tile 256x128 (8 warps, warp tile 64x64), K chunk 32 (32 chunks),
// 4-stage 24KB ring (96KB, 1 CTA/SM), single-thread mbarrier wait.
// Loads: 3 x 8KB cp.async.bulk per chunk (A-half0, A-half1, B).
// grid (8 nt, 4 mt, 16 z), block 256.
// ============================================================
#define STAGE_BYTES 24576
#define NSTAGE 4
#define GEMM_SMEM (NSTAGE * STAGE_BYTES + 32)

__global__ __launch_bounds__(256, 1) void gemm_mma_kernel(int stage) {
    extern __shared__ char smem[];
    const uint32_t sbase = smem_u32(smem);
    const uint32_t mbar  = sbase + NSTAGE * STAGE_BYTES;
    const int t    = threadIdx.x;
    const int lane = t & 31;
    const int wid  = t >> 5;

    const char *A, *B;
    if (stage == 0) { A = (const char*)g_Vf4; B = (const char*)g_Kf4; }
    else            { A = (const char*)g_Cf4; B = (const char*)g_Qf4; }
    const int z  = blockIdx.z;
    const int mt = blockIdx.y;     // 0..3, covers rows mt*256..mt*256+255
    const int nt = blockIdx.x;     // 0..7
    const char* gA0 = A + (size_t)(z * 8 + 2 * mt)     * 32 * 8192;
    const char* gA1 = A + (size_t)(z * 8 + 2 * mt + 1) * 32 * 8192;
    const char* gB  = B + (size_t)(z * 8 + nt)         * 32 * 8192;

    if (t == 0) {
#pragma unroll
        for (int s = 0; s < NSTAGE; s++) mbar_init(mbar + 8 * s, 1);
        asm volatile("fence.proxy.async.shared::cta;" ::: "memory");
    }
    __syncthreads();

    auto issue = [&](int kt) {
        const int st = kt & (NSTAGE - 1);
        const uint32_t mb = mbar + 8 * st;
        const uint32_t sb = sbase + st * STAGE_BYTES;
        mbar_expect_tx(mb, STAGE_BYTES);
        bulkcp(sb,         gA0 + (size_t)kt * 8192, 8192, mb);
        bulkcp(sb + 8192,  gA1 + (size_t)kt * 8192, 8192, mb);
        bulkcp(sb + 16384, gB  + (size_t)kt * 8192, 8192, mb);
    };
    if (t == 0) { issue(0); issue(1); issue(2); }

    // compute mapping: warp tile 64x64; wm = wid&3 (m), wn = wid>>2 (n)
    const int wm = wid & 3;
    const int wn = wid >> 2;
    const int aRloc = (wm & 1) * 64 + (lane & 15);   // row within the 128-row A half
    const int aHalf = wm >> 1;                       // 0 -> A0, 1 -> A1
    const int aHi   = lane >> 4;
    const int bR    = wn * 64 + (lane & 7) + ((lane >> 4) << 3);
    const int bHi   = (lane >> 3) & 1;

    float acc[4][8][4];
#pragma unroll
    for (int i = 0; i < 4; i++)
#pragma unroll
        for (int j = 0; j < 8; j++)
#pragma unroll
            for (int p = 0; p < 4; p++) acc[i][j][p] = 0.f;

#pragma unroll 1
    for (int kt = 0; kt < 32; kt++) {
        // single-waiter + bar.sync release (also closes reads of stage kt-1)
        if (t == 0) mbar_wait(mbar + 8 * (kt & 3), (kt >> 2) & 1);
        __syncthreads();
        if (t == 0 && kt + 3 < 32) issue(kt + 3);   // overwrites stage (kt-1)&3

        const uint32_t sb = sbase + (kt & 3) * STAGE_BYTES;
        const uint32_t ab = sb + aHalf * 8192;
        const uint32_t bb = sb + 16384;
#pragma unroll
        for (int ks = 0; ks < 2; ks++) {
            const int ch_a = ks * 2 + aHi;
            const int ch_b = ks * 2 + bHi;
            unsigned bf[4][4];
#pragma unroll
            for (int np = 0; np < 4; np++)
                ldsm4(bf[np], bb + swzoff(bR + np * 16, ch_b));
#pragma unroll
            for (int mb = 0; mb < 4; mb++) {
                unsigned ah[4];
                ldsm4(ah, ab + swzoff(aRloc + mb * 16, ch_a));
#pragma unroll
                for (int nb = 0; nb < 8; nb++)
                    mma16816(acc[mb][nb], ah, &bf[nb >> 1][(nb & 1) * 2]);
            }
        }
    }

    // ---- epilogue
    const int g  = lane >> 2;
    const int tt = lane & 3;
    const int mw = mt * 256 + wm * 64;
    const int nw = nt * 128 + wn * 64;

    if (stage == 0) {
        char* Cf = (char*)g_Cf4;
        const float sc = 1.f / 256.f;
#pragma unroll
        for (int mb = 0; mb < 4; mb++)
#pragma unroll
            for (int nb = 0; nb < 8; nb++) {
                const float* a = acc[mb][nb];
                int m = mw + mb * 16 + g;
                int k = nw + nb * 8 + 2 * tt;
                *(unsigned*)(Cf + pkoff(z, m,     k)) = packh2(a[0] * sc, a[1] * sc);
                *(unsigned*)(Cf + pkoff(z, m + 8, k)) = packh2(a[2] * sc, a[3] * sc);
            }
    } else {
        const float sc = SCALE / 256.f;
        const size_t zoff = (size_t)z << 20;
#pragma unroll
        for (int mb = 0; mb < 4; mb++)
#pragma unroll
            for (int nb = 0; nb < 8; nb++) {
                const float* a = acc[mb][nb];
                size_t base = zoff + (size_t)(mw + mb * 16 + g) * 1024 + nw + nb * 8 + 2 * tt;
                *(float2*)&g_X[base]            = make_float2(a[0] * sc, a[1] * sc);
                *(float2*)&g_X[base + 8 * 1024] = make_float2(a[2] * sc, a[3] * sc);
            }
    }
}

// ============================================================
// Kernel 5: output projection. Y[b,o,n] = b_out[o] + sum_c X[b,c,n]*w_out[o,c]
// ============================================================
__global__ __launch_bounds__(256) void proj_kernel(const float* __restrict__ wout,
                                                   const float* __restrict__ bout) {
    __shared__ float ws[32][64];
    const int b  = blockIdx.y;
    const int n  = blockIdx.x * 32 + (threadIdx.x & 31);
    const int og = threadIdx.x >> 5;
    const float* X = g_X + ((size_t)b << 22);

    float acc[4];
#pragma unroll
    for (int j = 0; j < 4; j++) acc[j] = bout[og * 4 + j];

    for (int c0 = 0; c0 < 4096; c0 += 64) {
        __syncthreads();
#pragma unroll
        for (int i = 0; i < 2; i++) {
            int idx = threadIdx.x + 256 * i;
            int o = idx >> 4, c4 = (idx & 15) << 2;
            *(float4*)&ws[o][c4] = *(const float4*)&wout[(size_t)o * 4096 + c0 + c4];
        }
        __syncthreads();
#pragma unroll 16
        for (int cl = 0; cl < 64; cl++) {
            float x = X[(size_t)(c0 + cl) * 1024 + n];
#pragma unroll
            for (int j = 0; j < 4; j++) acc[j] += ws[og * 4 + j][cl] * x;
        }
    }
#pragma unroll
    for (int j = 0; j < 4; j++)
        g_Y[((size_t)b * 32 + og * 4 + j) * 1024 + n] = acc[j];
}

// ============================================================
// Kernel 6: per-batch mean/var.
// ============================================================
__global__ __launch_bounds__(1024) void stats_kernel() {
    __shared__ float ss[32], ss2[32];
    const int b = blockIdx.x, t = threadIdx.x;
    const float* Y = g_Y + (size_t)b * 32768;
    float s = 0.f, s2 = 0.f;
#pragma unroll
    for (int k = 0; k < 32; k++) {
        float v = Y[t + 1024 * k];
        s += v; s2 += v * v;
    }
#pragma unroll
    for (int o = 16; o; o >>= 1) {
        s  += __shfl_xor_sync(0xffffffffu, s, o);
        s2 += __shfl_xor_sync(0xffffffffu, s2, o);
    }
    if ((t & 31) == 0) { ss[t >> 5] = s; ss2[t >> 5] = s2; }
    __syncthreads();
    if (t < 32) {
        s = ss[t]; s2 = ss2[t];
#pragma unroll
        for (int o = 16; o; o >>= 1) {
            s  += __shfl_xor_sync(0xffffffffu, s, o);
            s2 += __shfl_xor_sync(0xffffffffu, s2, o);
        }
        if (t == 0) {
            float mean = s * (1.f / 32768.f);
            g_stats[b]     = mean;
            g_stats[4 + b] = s2 * (1.f / 32768.f) - mean * mean;
        }
    }
}

// ============================================================
// Kernel 7: GroupNorm finalize -> d_out.
// ============================================================
__global__ void gn_kernel(const float* __restrict__ gamma,
                          const float* __restrict__ beta,
                          float* __restrict__ out) {
    int idx = blockIdx.x * 256 + threadIdx.x;
    int b = idx >> 15;
    int o = (idx >> 10) & 31;
    float mean = g_stats[b];
    float rstd = rsqrtf(g_stats[4 + b] + EPSGN);
    out[idx] = (g_Y[idx] - mean) * rstd * gamma[o] + beta[o];
}

// ============================================================
extern "C" void kernel_launch(void* const* d_in, const int* in_sizes, int n_in,
                              void* d_out, int out_size) {
    (void)in_sizes; (void)n_in; (void)out_size;
    const float* image = (const float*)d_in[0];
    const float* w_qkv = (const float*)d_in[1];
    const float* b_qkv = (const float*)d_in[2];
    const float* w_out = (const float*)d_in[3];
    const float* b_out = (const float*)d_in[4];
    const float* gamma = (const float*)d_in[5];
    const float* beta  = (const float*)d_in[6];
    float* out = (float*)d_out;

    cudaFuncSetAttribute(gemm_mma_kernel,
                         cudaFuncAttributeMaxDynamicSharedMemorySize, GEMM_SMEM);

    qkv_kernel<<<dim3(8, 192, 4), 256>>>(image, w_qkv, b_qkv);        // launch 1
    ksm_qsum_kernel<<<dim3(32, 16, 2), 1024>>>();                     // launch 2
    q_t_kernel<<<dim3(32, 32, 16), dim3(32, 8)>>>();                  // launch 3
    gemm_mma_kernel<<<dim3(8, 4, 16), 256, GEMM_SMEM>>>(0);           // launch 4 (profiled)
    gemm_mma_kernel<<<dim3(8, 4, 16), 256, GEMM_SMEM>>>(1);           // launch 5
    proj_kernel<<<dim3(32, 4), 256>>>(w_out, b_out);
    stats_kernel<<<4, 1024>>>();
    gn_kernel<<<512, 256>>>(gamma, beta, out);
}

// round 13
// speedup vs baseline: 1.9095x; 1.9095x over previous
#include <cuda_runtime.h>
#include <cuda_fp16.h>
#include <math.h>
#include <stdint.h>

// ---------------- problem constants ----------------
#define NB    4
#define NC    32
#define NSP   1024
#define ND    1024
#define NBH   16
#define SCALE 0.17677669529663687f   // 1/sqrt(32)
#define EPSGN 1e-5f

// ---------------- scratch (device globals; allocation-free) ----------------
__device__ float g_X  [NBH * ND * NSP];       // attention out [bh][e][n] fp32
__device__ float g_Y  [NB * NC * NSP];        // projection out, pre-GN
__device__ float g_Yp [NB * 8 * NC * NSP];    // proj partials [b][cg][o][n]
__device__ float g_pst[NB * 4 * 2];           // per-(b,og) partial {sum, sumsq}
__device__ float g_qinv[NBH * NSP];           // 256 / sum(exp(q)) per (z,n)

#define HFN (NBH * ND * NSP / 8)
// natural f16 [z][d][n]:
__device__ uint4 g_QH4[HFN];   // q pre-softmax f16
__device__ uint4 g_KH4[HFN];   // k pre-softmax f16
// TILE-PACKED + PRE-SWIZZLED f16 (blocks of 8192B = 128 rows x 64B):
__device__ uint4 g_Vf4[HFN];   // v  [e][n]
__device__ uint4 g_Kf4[HFN];   // 256*k-softmax [d][n]
__device__ uint4 g_Qf4[HFN];   // 256*q-softmax^T [n][d]
__device__ uint4 g_Cf4[HFN];   // ctx^T [e][d]

// ---------------- small helpers ----------------
__device__ __forceinline__ uint32_t smem_u32(const void* p) {
    uint32_t a;
    asm("{ .reg .u64 t; cvta.to.shared.u64 t, %1; cvt.u32.u64 %0, t; }" : "=r"(a) : "l"(p));
    return a;
}
__device__ __forceinline__ unsigned packh2(float a, float b) {
    __half2 p = __floats2half2_rn(a, b);
    return *reinterpret_cast<unsigned*>(&p);
}
// byte offset of element (row, k) of matrix z in packed-swizzled layout
__device__ __forceinline__ size_t pkoff(int z, int row, int k) {
    size_t blk = (size_t)(z * 8 + (row >> 7)) * 32 + (k >> 5);
    int r = row & 127, kk = k & 31;
    return blk * 8192 +
           (uint32_t)(r * 64 + ((((kk >> 3) + (r >> 1)) & 3) << 4) + (kk & 7) * 2);
}
__device__ __forceinline__ uint32_t swzoff(int R, int ch) {
    return (uint32_t)(R * 64 + (((ch + (R >> 1)) & 3) << 4));
}
__device__ __forceinline__ void mbar_init(uint32_t a, uint32_t cnt) {
    asm volatile("mbarrier.init.shared.b64 [%0], %1;" :: "r"(a), "r"(cnt) : "memory");
}
__device__ __forceinline__ void mbar_expect_tx(uint32_t a, uint32_t tx) {
    asm volatile("mbarrier.arrive.expect_tx.shared.b64 _, [%0], %1;"
                 :: "r"(a), "r"(tx) : "memory");
}
__device__ __forceinline__ void mbar_wait(uint32_t a, uint32_t phase) {
    asm volatile(
        "{\n\t.reg .pred P;\n"
        "W%=:\n\t"
        "mbarrier.try_wait.parity.shared::cta.b64 P, [%0], %1;\n\t"
        "@!P bra W%=;\n\t}"
        :: "r"(a), "r"(phase) : "memory");
}
__device__ __forceinline__ void bulkcp(uint32_t sdst, const void* gsrc,
                                       uint32_t bytes, uint32_t mb) {
    asm volatile(
        "cp.async.bulk.shared::cta.global.mbarrier::complete_tx::bytes [%0], [%1], %2, [%3];"
        :: "r"(sdst), "l"(gsrc), "r"(bytes), "r"(mb) : "memory");
}
__device__ __forceinline__ void ldsm4(unsigned* r, uint32_t addr) {
    asm volatile("ldmatrix.sync.aligned.m8n8.x4.shared.b16 {%0,%1,%2,%3}, [%4];"
                 : "=r"(r[0]), "=r"(r[1]), "=r"(r[2]), "=r"(r[3]) : "r"(addr));
}
__device__ __forceinline__ void mma16816(float* c, const unsigned* a, const unsigned* b) {
    asm volatile(
        "mma.sync.aligned.m16n8k16.row.col.f32.f16.f16.f32 "
        "{%0,%1,%2,%3}, {%4,%5,%6,%7}, {%8,%9}, {%0,%1,%2,%3};"
        : "+f"(c[0]), "+f"(c[1]), "+f"(c[2]), "+f"(c[3])
        : "r"(a[0]), "r"(a[1]), "r"(a[2]), "r"(a[3]), "r"(b[0]), "r"(b[1]));
}

// ============================================================
// Kernel 1: QKV projection. q,k -> f16 natural [d][n]; v -> f16 packed.
// ============================================================
__global__ __launch_bounds__(256) void qkv_kernel(const float* __restrict__ img,
                                                  const float* __restrict__ w,
                                                  const float* __restrict__ bias) {
    __shared__ float xs[32][128];
    __shared__ float ws[64][32];
    __shared__ float bs[64];

    const int b  = blockIdx.z;
    const int o0 = blockIdx.y * 64;
    const int n0 = blockIdx.x * 128;
    const int t  = threadIdx.x;

#pragma unroll
    for (int i = 0; i < 4; i++) {
        int idx = t + 256 * i;
        int c = idx >> 5, c4 = (idx & 31) << 2;
        *(float4*)&xs[c][c4] = *(const float4*)&img[((size_t)b * 32 + c) * 1024 + n0 + c4];
    }
#pragma unroll
    for (int i = 0; i < 2; i++) {
        int idx = t + 256 * i;
        int o = idx >> 3, c4 = (idx & 7) << 2;
        *(float4*)&ws[o][c4] = *(const float4*)&w[(size_t)(o0 + o) * 32 + c4];
    }
    if (t < 64) bs[t] = bias[o0 + t];
    __syncthreads();

    const int tx = t & 31;
    const int oy = t >> 5;

    float acc[8][4];
#pragma unroll
    for (int r = 0; r < 8; r++) {
        float bv = bs[8 * oy + r];
#pragma unroll
        for (int i = 0; i < 4; i++) acc[r][i] = bv;
    }
#pragma unroll
    for (int c = 0; c < 32; c++) {
        float4 x = *(const float4*)&xs[c][4 * tx];
#pragma unroll
        for (int r = 0; r < 8; r++) {
            float wv = ws[8 * oy + r][c];
            acc[r][0] += wv * x.x; acc[r][1] += wv * x.y;
            acc[r][2] += wv * x.z; acc[r][3] += wv * x.w;
        }
    }

    const int nglob = n0 + 4 * tx;
#pragma unroll
    for (int r = 0; r < 8; r++) {
        int o     = o0 + 8 * oy + r;
        int which = o >> 12;
        int oc    = o & 4095;
        int h     = oc & 3;
        int cch   = oc >> 2;
        int zz    = b * 4 + h;
        uint2 hv;
        hv.x = packh2(acc[r][0], acc[r][1]);
        hv.y = packh2(acc[r][2], acc[r][3]);
        if (which == 2) {
            *(uint2*)((char*)g_Vf4 + pkoff(zz, cch, nglob)) = hv;
        } else {
            __half* dst = (which == 0) ? (__half*)g_QH4 : (__half*)g_KH4;
            *(uint2*)&dst[((size_t)zz << 20) + (size_t)cch * 1024 + nglob] = hv;
        }
    }
}

// ============================================================
// Kernel 2 (fused dual-role): z-slice 0 -> k softmax (x256, f16 packed);
// z-slice 1 -> q denominator g_qinv[z][n] = 256 / sum_d exp(q[d][n]).
// grid (32, 16, 2), block 1024.
// ============================================================
__global__ __launch_bounds__(1024) void ksm_qsum_kernel() {
    const int z = blockIdx.y;
    if (blockIdx.z == 0) {
        const int lane = threadIdx.x & 31;
        const int w    = threadIdx.x >> 5;
        const int d    = blockIdx.x * 32 + w;
        const __half2* src =
            (const __half2*)((const __half*)g_KH4 + ((size_t)z << 20) + (size_t)d * 1024);

        float2 vals[16];
        float m = -3.402823466e38f;
#pragma unroll
        for (int j = 0; j < 16; j++) {
            __half2 h = src[j * 32 + lane];
            vals[j] = __half22float2(h);
            m = fmaxf(m, fmaxf(vals[j].x, vals[j].y));
        }
#pragma unroll
        for (int o = 16; o; o >>= 1) m = fmaxf(m, __shfl_xor_sync(0xffffffffu, m, o));
        float s = 0.f;
#pragma unroll
        for (int j = 0; j < 16; j++) {
            vals[j].x = expf(vals[j].x - m);
            vals[j].y = expf(vals[j].y - m);
            s += vals[j].x + vals[j].y;
        }
#pragma unroll
        for (int o = 16; o; o >>= 1) s += __shfl_xor_sync(0xffffffffu, s, o);
        float inv = 256.f / s;

        char* KfB = (char*)g_Kf4;
#pragma unroll
        for (int j = 0; j < 16; j++) {
            unsigned u = packh2(vals[j].x * inv, vals[j].y * inv);
            *(unsigned*)(KfB + pkoff(z, d, j * 64 + 2 * lane)) = u;
        }
    } else {
        __shared__ float red[32][32];
        const int nl = threadIdx.x & 31;
        const int dg = threadIdx.x >> 5;
        const int n  = blockIdx.x * 32 + nl;
        const __half* src = (const __half*)g_QH4 + ((size_t)z << 20) + n;

        float s = 0.f;
#pragma unroll 8
        for (int d = dg * 32; d < dg * 32 + 32; d++)
            s += expf(__half2float(src[(size_t)d * 1024]));
        red[dg][nl] = s;
        __syncthreads();
        if (dg == 0) {
            float tot = 0.f;
#pragma unroll
            for (int r = 0; r < 32; r++) tot += red[r][nl];
            g_qinv[z * 1024 + n] = 256.f / tot;
        }
    }
}

// ============================================================
// Kernel 3: q softmax-apply (x256) + transpose -> f16 packed qT[n][d].
// ============================================================
__global__ void q_t_kernel() {
    __shared__ float s[32][33];
    const int z  = blockIdx.z;
    const int d0 = blockIdx.y * 32;
    const int n0 = blockIdx.x * 32;
    const int tx = threadIdx.x, ty = threadIdx.y;
    const __half* src = (const __half*)g_QH4 + ((size_t)z << 20);
    const float inv = g_qinv[z * 1024 + n0 + tx];

#pragma unroll
    for (int i = 0; i < 4; i++) {
        int r = ty + 8 * i;
        s[r][tx] = expf(__half2float(src[(size_t)(d0 + r) * 1024 + n0 + tx])) * inv;
    }
    __syncthreads();

    char* QfB = (char*)g_Qf4;
#pragma unroll
    for (int i = 0; i < 4; i++) {
        int nl = ty + 8 * i;
        *(__half*)(QfB + pkoff(z, n0 + nl, d0 + tx)) = __float2half_rn(s[tx][nl]);
    }
}

// ============================================================
// Kernel 4: single-pass f16 TN GEMM, bulk-TMA loads + mma.sync.
// CTA tile 256x128 (8 warps, warp tile 64x64), K chunk 32 (32 chunks),
// 4-stage 24KB ring; LDSMs batched ahead of HMMA block per k16.
// grid (8 nt, 4 mt, 16 z), block 256.
// ============================================================
#define STAGE_BYTES 24576
#define NSTAGE 4
#define GEMM_SMEM (NSTAGE * STAGE_BYTES + 32)

__global__ __launch_bounds__(256, 1) void gemm_mma_kernel(int stage) {
    extern __shared__ char smem[];
    const uint32_t sbase = smem_u32(smem);
    const uint32_t mbar  = sbase + NSTAGE * STAGE_BYTES;
    const int t    = threadIdx.x;
    const int lane = t & 31;
    const int wid  = t >> 5;

    const char *A, *B;
    if (stage == 0) { A = (const char*)g_Vf4; B = (const char*)g_Kf4; }
    else            { A = (const char*)g_Cf4; B = (const char*)g_Qf4; }
    const int z  = blockIdx.z;
    const int mt = blockIdx.y;
    const int nt = blockIdx.x;
    const char* gA0 = A + (size_t)(z * 8 + 2 * mt)     * 32 * 8192;
    const char* gA1 = A + (size_t)(z * 8 + 2 * mt + 1) * 32 * 8192;
    const char* gB  = B + (size_t)(z * 8 + nt)         * 32 * 8192;

    if (t == 0) {
#pragma unroll
        for (int s = 0; s < NSTAGE; s++) mbar_init(mbar + 8 * s, 1);
        asm volatile("fence.proxy.async.shared::cta;" ::: "memory");
    }
    __syncthreads();

    auto issue = [&](int kt) {
        const int st = kt & (NSTAGE - 1);
        const uint32_t mb = mbar + 8 * st;
        const uint32_t sb = sbase + st * STAGE_BYTES;
        mbar_expect_tx(mb, STAGE_BYTES);
        bulkcp(sb,         gA0 + (size_t)kt * 8192, 8192, mb);
        bulkcp(sb + 8192,  gA1 + (size_t)kt * 8192, 8192, mb);
        bulkcp(sb + 16384, gB  + (size_t)kt * 8192, 8192, mb);
    };
    if (t == 0) { issue(0); issue(1); issue(2); }

    const int wm = wid & 3;
    const int wn = wid >> 2;
    const int aRloc = (wm & 1) * 64 + (lane & 15);
    const int aHalf = wm >> 1;
    const int aHi   = lane >> 4;
    const int bR    = wn * 64 + (lane & 7) + ((lane >> 4) << 3);
    const int bHi   = (lane >> 3) & 1;

    float acc[4][8][4];
#pragma unroll
    for (int i = 0; i < 4; i++)
#pragma unroll
        for (int j = 0; j < 8; j++)
#pragma unroll
            for (int p = 0; p < 4; p++) acc[i][j][p] = 0.f;

#pragma unroll 1
    for (int kt = 0; kt < 32; kt++) {
        if (t == 0) mbar_wait(mbar + 8 * (kt & 3), (kt >> 2) & 1);
        __syncthreads();
        if (t == 0 && kt + 3 < 32) issue(kt + 3);

        const uint32_t sb = sbase + (kt & 3) * STAGE_BYTES;
        const uint32_t ab = sb + aHalf * 8192;
        const uint32_t bb = sb + 16384;
#pragma unroll
        for (int ks = 0; ks < 2; ks++) {
            const int ch_a = ks * 2 + aHi;
            const int ch_b = ks * 2 + bHi;
            unsigned bf[4][4], ah[4][4];
#pragma unroll
            for (int np = 0; np < 4; np++)
                ldsm4(bf[np], bb + swzoff(bR + np * 16, ch_b));
#pragma unroll
            for (int mb = 0; mb < 4; mb++)
                ldsm4(ah[mb], ab + swzoff(aRloc + mb * 16, ch_a));
#pragma unroll
            for (int mb = 0; mb < 4; mb++)
#pragma unroll
                for (int nb = 0; nb < 8; nb++)
                    mma16816(acc[mb][nb], ah[mb], &bf[nb >> 1][(nb & 1) * 2]);
        }
    }

    // ---- epilogue
    const int g  = lane >> 2;
    const int tt = lane & 3;
    const int mw = mt * 256 + wm * 64;
    const int nw = nt * 128 + wn * 64;

    if (stage == 0) {
        char* Cf = (char*)g_Cf4;
        const float sc = 1.f / 256.f;
#pragma unroll
        for (int mb = 0; mb < 4; mb++)
#pragma unroll
            for (int nb = 0; nb < 8; nb++) {
                const float* a = acc[mb][nb];
                int m = mw + mb * 16 + g;
                int k = nw + nb * 8 + 2 * tt;
                *(unsigned*)(Cf + pkoff(z, m,     k)) = packh2(a[0] * sc, a[1] * sc);
                *(unsigned*)(Cf + pkoff(z, m + 8, k)) = packh2(a[2] * sc, a[3] * sc);
            }
    } else {
        const float sc = SCALE / 256.f;
        const size_t zoff = (size_t)z << 20;
#pragma unroll
        for (int mb = 0; mb < 4; mb++)
#pragma unroll
            for (int nb = 0; nb < 8; nb++) {
                const float* a = acc[mb][nb];
                size_t base = zoff + (size_t)(mw + mb * 16 + g) * 1024 + nw + nb * 8 + 2 * tt;
                *(float2*)&g_X[base]            = make_float2(a[0] * sc, a[1] * sc);
                *(float2*)&g_X[base + 8 * 1024] = make_float2(a[2] * sc, a[3] * sc);
            }
    }
}

// ============================================================
// Kernel 5: output projection PARTIALS.
// Yp[b][cg][o][n] = sum_{c in cg-chunk} X[b,c,n]*w_out[o,c]
// grid (32 nt, 4 b, 8 cg), block 256 (32 n x 8 og of 4 outputs).
// ============================================================
__global__ __launch_bounds__(256) void proj_kernel(const float* __restrict__ wout) {
    __shared__ float ws[32][64];
    const int b  = blockIdx.y;
    const int cg = blockIdx.z;
    const int n  = blockIdx.x * 32 + (threadIdx.x & 31);
    const int og = threadIdx.x >> 5;
    const float* X = g_X + ((size_t)b << 22);

    float acc[4] = {0.f, 0.f, 0.f, 0.f};

    for (int c0 = cg * 512; c0 < cg * 512 + 512; c0 += 64) {
        __syncthreads();
#pragma unroll
        for (int i = 0; i < 2; i++) {
            int idx = threadIdx.x + 256 * i;
            int o = idx >> 4, c4 = (idx & 15) << 2;
            *(float4*)&ws[o][c4] = *(const float4*)&wout[(size_t)o * 4096 + c0 + c4];
        }
        __syncthreads();
#pragma unroll 16
        for (int cl = 0; cl < 64; cl++) {
            float x = X[(size_t)(c0 + cl) * 1024 + n];
#pragma unroll
            for (int j = 0; j < 4; j++) acc[j] += ws[og * 4 + j][cl] * x;
        }
    }
#pragma unroll
    for (int j = 0; j < 4; j++)
        g_Yp[(((size_t)b * 8 + cg) * 32 + og * 4 + j) * 1024 + n] = acc[j];
}

// ============================================================
// Kernel 6: finalize — Y = bias + sum_cg Yp; per-(b,og) stat partials.
// grid (16): b = bx>>2, og = bx&3 (8 o each). block 1024 (one n per thread).
// ============================================================
__global__ __launch_bounds__(1024) void finalize_kernel(const float* __restrict__ bout) {
    __shared__ float ss[32], ss2[32];
    const int b  = blockIdx.x >> 2;
    const int og = blockIdx.x & 3;
    const int t  = threadIdx.x;   // n
    const float* Yp = g_Yp + (size_t)b * 8 * 32 * 1024;

    float s = 0.f, s2 = 0.f;
#pragma unroll
    for (int oo = 0; oo < 8; oo++) {
        int o = og * 8 + oo;
        float y = bout[o];
#pragma unroll
        for (int cgi = 0; cgi < 8; cgi++)
            y += Yp[((size_t)cgi * 32 + o) * 1024 + t];
        g_Y[((size_t)b * 32 + o) * 1024 + t] = y;
        s += y; s2 += y * y;
    }
#pragma unroll
    for (int o = 16; o; o >>= 1) {
        s  += __shfl_xor_sync(0xffffffffu, s, o);
        s2 += __shfl_xor_sync(0xffffffffu, s2, o);
    }
    if ((t & 31) == 0) { ss[t >> 5] = s; ss2[t >> 5] = s2; }
    __syncthreads();
    if (t < 32) {
        s = ss[t]; s2 = ss2[t];
#pragma unroll
        for (int o = 16; o; o >>= 1) {
            s  += __shfl_xor_sync(0xffffffffu, s, o);
            s2 += __shfl_xor_sync(0xffffffffu, s2, o);
        }
        if (t == 0) {
            g_pst[(b * 4 + og) * 2]     = s;
            g_pst[(b * 4 + og) * 2 + 1] = s2;
        }
    }
}

// ============================================================
// Kernel 7: GroupNorm finalize -> d_out (combines 4 stat partials per batch).
// ============================================================
__global__ void gn_kernel(const float* __restrict__ gamma,
                          const float* __restrict__ beta,
                          float* __restrict__ out) {
    int idx = blockIdx.x * 256 + threadIdx.x;
    int b = idx >> 15;
    int o = (idx >> 10) & 31;
    float s  = g_pst[b * 8]     + g_pst[b * 8 + 2] + g_pst[b * 8 + 4] + g_pst[b * 8 + 6];
    float s2 = g_pst[b * 8 + 1] + g_pst[b * 8 + 3] + g_pst[b * 8 + 5] + g_pst[b * 8 + 7];
    float mean = s * (1.f / 32768.f);
    float var  = s2 * (1.f / 32768.f) - mean * mean;
    float rstd = rsqrtf(var + EPSGN);
    out[idx] = (g_Y[idx] - mean) * rstd * gamma[o] + beta[o];
}

// ============================================================
extern "C" void kernel_launch(void* const* d_in, const int* in_sizes, int n_in,
                              void* d_out, int out_size) {
    (void)in_sizes; (void)n_in; (void)out_size;
    const float* image = (const float*)d_in[0];
    const float* w_qkv = (const float*)d_in[1];
    const float* b_qkv = (const float*)d_in[2];
    const float* w_out = (const float*)d_in[3];
    const float* b_out = (const float*)d_in[4];
    const float* gamma = (const float*)d_in[5];
    const float* beta  = (const float*)d_in[6];
    float* out = (float*)d_out;

    cudaFuncSetAttribute(gemm_mma_kernel,
                         cudaFuncAttributeMaxDynamicSharedMemorySize, GEMM_SMEM);

    qkv_kernel<<<dim3(8, 192, 4), 256>>>(image, w_qkv, b_qkv);        // 1
    ksm_qsum_kernel<<<dim3(32, 16, 2), 1024>>>();                     // 2
    q_t_kernel<<<dim3(32, 32, 16), dim3(32, 8)>>>();                  // 3
    gemm_mma_kernel<<<dim3(8, 4, 16), 256, GEMM_SMEM>>>(0);           // 4 (profiled)
    gemm_mma_kernel<<<dim3(8, 4, 16), 256, GEMM_SMEM>>>(1);           // 5
    proj_kernel<<<dim3(32, 4, 8), 256>>>(w_out);                      // 6
    finalize_kernel<<<16, 1024>>>(b_out);                             // 7
    gn_kernel<<<512, 256>>>(gamma, beta, out);                        // 8
}

// round 14
// speedup vs baseline: 1.9218x; 1.0064x over previous
#include <cuda_runtime.h>
#include <cuda_fp16.h>
#include <math.h>
#include <stdint.h>

// ---------------- problem constants ----------------
#define NB    4
#define NC    32
#define NSP   1024
#define ND    1024
#define NBH   16
#define SCALE 0.17677669529663687f   // 1/sqrt(32)
#define EPSGN 1e-5f

// ---------------- scratch (device globals; allocation-free) ----------------
__device__ float g_Y  [NB * NC * NSP];        // projection out, pre-GN
__device__ float g_Yp [NB * 8 * NC * NSP];    // proj partials [b][cg][o][n]
__device__ float g_pst[NB * 4 * 2];           // per-(b,og) partial {sum, sumsq}

#define HFN (NBH * ND * NSP / 8)
// natural f16 [z][d][n]:
__device__ uint4 g_QH4[HFN];   // q pre-softmax f16
__device__ uint4 g_KH4[HFN];   // k pre-softmax f16
__device__ uint4 g_Xh4[HFN];   // attention out [z][e][n] f16
// TILE-PACKED + PRE-SWIZZLED f16 (blocks of 8192B = 128 rows x 64B):
__device__ uint4 g_Vf4[HFN];   // v  [e][n]
__device__ uint4 g_Kf4[HFN];   // 256*k-softmax [d][n]
__device__ uint4 g_Qf4[HFN];   // 256*q-softmax^T [n][d]
__device__ uint4 g_Cf4[HFN];   // ctx^T [e][d]

// ---------------- small helpers ----------------
__device__ __forceinline__ uint32_t smem_u32(const void* p) {
    uint32_t a;
    asm("{ .reg .u64 t; cvta.to.shared.u64 t, %1; cvt.u32.u64 %0, t; }" : "=r"(a) : "l"(p));
    return a;
}
__device__ __forceinline__ unsigned packh2(float a, float b) {
    __half2 p = __floats2half2_rn(a, b);
    return *reinterpret_cast<unsigned*>(&p);
}
// byte offset of element (row, k) of matrix z in packed-swizzled layout
__device__ __forceinline__ size_t pkoff(int z, int row, int k) {
    size_t blk = (size_t)(z * 8 + (row >> 7)) * 32 + (k >> 5);
    int r = row & 127, kk = k & 31;
    return blk * 8192 +
           (uint32_t)(r * 64 + ((((kk >> 3) + (r >> 1)) & 3) << 4) + (kk & 7) * 2);
}
__device__ __forceinline__ uint32_t swzoff(int R, int ch) {
    return (uint32_t)(R * 64 + (((ch + (R >> 1)) & 3) << 4));
}
__device__ __forceinline__ void mbar_init(uint32_t a, uint32_t cnt) {
    asm volatile("mbarrier.init.shared.b64 [%0], %1;" :: "r"(a), "r"(cnt) : "memory");
}
__device__ __forceinline__ void mbar_expect_tx(uint32_t a, uint32_t tx) {
    asm volatile("mbarrier.arrive.expect_tx.shared.b64 _, [%0], %1;"
                 :: "r"(a), "r"(tx) : "memory");
}
__device__ __forceinline__ void mbar_wait(uint32_t a, uint32_t phase) {
    asm volatile(
        "{\n\t.reg .pred P;\n"
        "W%=:\n\t"
        "mbarrier.try_wait.parity.shared::cta.b64 P, [%0], %1;\n\t"
        "@!P bra W%=;\n\t}"
        :: "r"(a), "r"(phase) : "memory");
}
__device__ __forceinline__ void bulkcp(uint32_t sdst, const void* gsrc,
                                       uint32_t bytes, uint32_t mb) {
    asm volatile(
        "cp.async.bulk.shared::cta.global.mbarrier::complete_tx::bytes [%0], [%1], %2, [%3];"
        :: "r"(sdst), "l"(gsrc), "r"(bytes), "r"(mb) : "memory");
}
__device__ __forceinline__ void ldsm4(unsigned* r, uint32_t addr) {
    asm volatile("ldmatrix.sync.aligned.m8n8.x4.shared.b16 {%0,%1,%2,%3}, [%4];"
                 : "=r"(r[0]), "=r"(r[1]), "=r"(r[2]), "=r"(r[3]) : "r"(addr));
}
__device__ __forceinline__ void mma16816(float* c, const unsigned* a, const unsigned* b) {
    asm volatile(
        "mma.sync.aligned.m16n8k16.row.col.f32.f16.f16.f32 "
        "{%0,%1,%2,%3}, {%4,%5,%6,%7}, {%8,%9}, {%0,%1,%2,%3};"
        : "+f"(c[0]), "+f"(c[1]), "+f"(c[2]), "+f"(c[3])
        : "r"(a[0]), "r"(a[1]), "r"(a[2]), "r"(a[3]), "r"(b[0]), "r"(b[1]));
}

// ============================================================
// Kernel 1: QKV projection. q,k -> f16 natural [d][n]; v -> f16 packed.
// ============================================================
__global__ __launch_bounds__(256) void qkv_kernel(const float* __restrict__ img,
                                                  const float* __restrict__ w,
                                                  const float* __restrict__ bias) {
    __shared__ float xs[32][128];
    __shared__ float ws[64][32];
    __shared__ float bs[64];

    const int b  = blockIdx.z;
    const int o0 = blockIdx.y * 64;
    const int n0 = blockIdx.x * 128;
    const int t  = threadIdx.x;

#pragma unroll
    for (int i = 0; i < 4; i++) {
        int idx = t + 256 * i;
        int c = idx >> 5, c4 = (idx & 31) << 2;
        *(float4*)&xs[c][c4] = *(const float4*)&img[((size_t)b * 32 + c) * 1024 + n0 + c4];
    }
#pragma unroll
    for (int i = 0; i < 2; i++) {
        int idx = t + 256 * i;
        int o = idx >> 3, c4 = (idx & 7) << 2;
        *(float4*)&ws[o][c4] = *(const float4*)&w[(size_t)(o0 + o) * 32 + c4];
    }
    if (t < 64) bs[t] = bias[o0 + t];
    __syncthreads();

    const int tx = t & 31;
    const int oy = t >> 5;

    float acc[8][4];
#pragma unroll
    for (int r = 0; r < 8; r++) {
        float bv = bs[8 * oy + r];
#pragma unroll
        for (int i = 0; i < 4; i++) acc[r][i] = bv;
    }
#pragma unroll
    for (int c = 0; c < 32; c++) {
        float4 x = *(const float4*)&xs[c][4 * tx];
#pragma unroll
        for (int r = 0; r < 8; r++) {
            float wv = ws[8 * oy + r][c];
            acc[r][0] += wv * x.x; acc[r][1] += wv * x.y;
            acc[r][2] += wv * x.z; acc[r][3] += wv * x.w;
        }
    }

    const int nglob = n0 + 4 * tx;
#pragma unroll
    for (int r = 0; r < 8; r++) {
        int o     = o0 + 8 * oy + r;
        int which = o >> 12;
        int oc    = o & 4095;
        int h     = oc & 3;
        int cch   = oc >> 2;
        int zz    = b * 4 + h;
        uint2 hv;
        hv.x = packh2(acc[r][0], acc[r][1]);
        hv.y = packh2(acc[r][2], acc[r][3]);
        if (which == 2) {
            *(uint2*)((char*)g_Vf4 + pkoff(zz, cch, nglob)) = hv;
        } else {
            __half* dst = (which == 0) ? (__half*)g_QH4 : (__half*)g_KH4;
            *(uint2*)&dst[((size_t)zz << 20) + (size_t)cch * 1024 + nglob] = hv;
        }
    }
}

// ============================================================
// Kernel 2 (fused dual-role):
// z-slice 0 -> k softmax over n (x256, f16 packed [d][n]);
// z-slice 1 -> FULL q path: denominator + softmax-apply (x256) + transpose
//              -> f16 packed qT[n][d]. vals stay in registers throughout.
// grid (32, 16, 2), block 1024.
// ============================================================
__global__ __launch_bounds__(1024) void ksm_q_kernel() {
    const int z = blockIdx.y;
    if (blockIdx.z == 0) {
        const int lane = threadIdx.x & 31;
        const int w    = threadIdx.x >> 5;
        const int d    = blockIdx.x * 32 + w;
        const __half2* src =
            (const __half2*)((const __half*)g_KH4 + ((size_t)z << 20) + (size_t)d * 1024);

        float2 vals[16];
        float m = -3.402823466e38f;
#pragma unroll
        for (int j = 0; j < 16; j++) {
            __half2 h = src[j * 32 + lane];
            vals[j] = __half22float2(h);
            m = fmaxf(m, fmaxf(vals[j].x, vals[j].y));
        }
#pragma unroll
        for (int o = 16; o; o >>= 1) m = fmaxf(m, __shfl_xor_sync(0xffffffffu, m, o));
        float s = 0.f;
#pragma unroll
        for (int j = 0; j < 16; j++) {
            vals[j].x = expf(vals[j].x - m);
            vals[j].y = expf(vals[j].y - m);
            s += vals[j].x + vals[j].y;
        }
#pragma unroll
        for (int o = 16; o; o >>= 1) s += __shfl_xor_sync(0xffffffffu, s, o);
        float inv = 256.f / s;

        char* KfB = (char*)g_Kf4;
#pragma unroll
        for (int j = 0; j < 16; j++) {
            unsigned u = packh2(vals[j].x * inv, vals[j].y * inv);
            *(unsigned*)(KfB + pkoff(z, d, j * 64 + 2 * lane)) = u;
        }
    } else {
        __shared__ float red[32][32];
        __shared__ float rinv[32];
        const int nl = threadIdx.x & 31;
        const int dg = threadIdx.x >> 5;
        const int n  = blockIdx.x * 32 + nl;
        const __half* src = (const __half*)g_QH4 + ((size_t)z << 20) + n;

        float vals[32];
        float s = 0.f;
#pragma unroll
        for (int j = 0; j < 32; j++) {
            vals[j] = expf(__half2float(src[(size_t)(dg * 32 + j) * 1024]));
            s += vals[j];
        }
        red[dg][nl] = s;
        __syncthreads();
        if (dg == 0) {
            float tot = 0.f;
#pragma unroll
            for (int r = 0; r < 32; r++) tot += red[r][nl];
            rinv[nl] = 256.f / tot;
        }
        __syncthreads();
        float inv = rinv[nl];

        char* QfB = (char*)g_Qf4;
#pragma unroll
        for (int g = 0; g < 4; g++) {
            uint4 u;
            u.x = packh2(vals[g * 8 + 0] * inv, vals[g * 8 + 1] * inv);
            u.y = packh2(vals[g * 8 + 2] * inv, vals[g * 8 + 3] * inv);
            u.z = packh2(vals[g * 8 + 4] * inv, vals[g * 8 + 5] * inv);
            u.w = packh2(vals[g * 8 + 6] * inv, vals[g * 8 + 7] * inv);
            *(uint4*)(QfB + pkoff(z, n, dg * 32 + g * 8)) = u;
        }
    }
}

// ============================================================
// Kernel 3: single-pass f16 TN GEMM, bulk-TMA loads + mma.sync.
// CTA tile 256x128 (8 warps, warp tile 64x64), K chunk 32 (32 chunks),
// 4-stage 24KB ring; BOTH k16 fragment sets loaded up front (double-
// buffered regs) so the LDSM latency head is paid once per 64 HMMAs.
// stage 0 -> Cf f16 packed (x 1/256); stage 1 -> Xh f16 natural (x SCALE/256).
// grid (8 nt, 4 mt, 16 z), block 256.
// ============================================================
#define STAGE_BYTES 24576
#define NSTAGE 4
#define GEMM_SMEM (NSTAGE * STAGE_BYTES + 32)

__global__ __launch_bounds__(256, 1) void gemm_mma_kernel(int stage) {
    extern __shared__ char smem[];
    const uint32_t sbase = smem_u32(smem);
    const uint32_t mbar  = sbase + NSTAGE * STAGE_BYTES;
    const int t    = threadIdx.x;
    const int lane = t & 31;
    const int wid  = t >> 5;

    const char *A, *B;
    if (stage == 0) { A = (const char*)g_Vf4; B = (const char*)g_Kf4; }
    else            { A = (const char*)g_Cf4; B = (const char*)g_Qf4; }
    const int z  = blockIdx.z;
    const int mt = blockIdx.y;
    const int nt = blockIdx.x;
    const char* gA0 = A + (size_t)(z * 8 + 2 * mt)     * 32 * 8192;
    const char* gA1 = A + (size_t)(z * 8 + 2 * mt + 1) * 32 * 8192;
    const char* gB  = B + (size_t)(z * 8 + nt)         * 32 * 8192;

    if (t == 0) {
#pragma unroll
        for (int s = 0; s < NSTAGE; s++) mbar_init(mbar + 8 * s, 1);
        asm volatile("fence.proxy.async.shared::cta;" ::: "memory");
    }
    __syncthreads();

    auto issue = [&](int kt) {
        const int st = kt & (NSTAGE - 1);
        const uint32_t mb = mbar + 8 * st;
        const uint32_t sb = sbase + st * STAGE_BYTES;
        mbar_expect_tx(mb, STAGE_BYTES);
        bulkcp(sb,         gA0 + (size_t)kt * 8192, 8192, mb);
        bulkcp(sb + 8192,  gA1 + (size_t)kt * 8192, 8192, mb);
        bulkcp(sb + 16384, gB  + (size_t)kt * 8192, 8192, mb);
    };
    if (t == 0) { issue(0); issue(1); issue(2); }

    const int wm = wid & 3;
    const int wn = wid >> 2;
    const int aRloc = (wm & 1) * 64 + (lane & 15);
    const int aHalf = wm >> 1;
    const int aHi   = lane >> 4;
    const int bR    = wn * 64 + (lane & 7) + ((lane >> 4) << 3);
    const int bHi   = (lane >> 3) & 1;

    float acc[4][8][4];
#pragma unroll
    for (int i = 0; i < 4; i++)
#pragma unroll
        for (int j = 0; j < 8; j++)
#pragma unroll
            for (int p = 0; p < 4; p++) acc[i][j][p] = 0.f;

#pragma unroll 1
    for (int kt = 0; kt < 32; kt++) {
        if (t == 0) mbar_wait(mbar + 8 * (kt & 3), (kt >> 2) & 1);
        __syncthreads();
        if (t == 0 && kt + 3 < 32) issue(kt + 3);

        const uint32_t sb = sbase + (kt & 3) * STAGE_BYTES;
        const uint32_t ab = sb + aHalf * 8192;
        const uint32_t bb = sb + 16384;

        // load BOTH k16 fragment sets up front
        unsigned a0[4][4], b0[4][4], a1[4][4], b1[4][4];
#pragma unroll
        for (int np = 0; np < 4; np++) {
            ldsm4(b0[np], bb + swzoff(bR + np * 16, bHi));
            ldsm4(b1[np], bb + swzoff(bR + np * 16, 2 + bHi));
        }
#pragma unroll
        for (int mb = 0; mb < 4; mb++) {
            ldsm4(a0[mb], ab + swzoff(aRloc + mb * 16, aHi));
            ldsm4(a1[mb], ab + swzoff(aRloc + mb * 16, 2 + aHi));
        }
#pragma unroll
        for (int mb = 0; mb < 4; mb++)
#pragma unroll
            for (int nb = 0; nb < 8; nb++)
                mma16816(acc[mb][nb], a0[mb], &b0[nb >> 1][(nb & 1) * 2]);
#pragma unroll
        for (int mb = 0; mb < 4; mb++)
#pragma unroll
            for (int nb = 0; nb < 8; nb++)
                mma16816(acc[mb][nb], a1[mb], &b1[nb >> 1][(nb & 1) * 2]);
    }

    // ---- epilogue
    const int g  = lane >> 2;
    const int tt = lane & 3;
    const int mw = mt * 256 + wm * 64;
    const int nw = nt * 128 + wn * 64;

    if (stage == 0) {
        char* Cf = (char*)g_Cf4;
        const float sc = 1.f / 256.f;
#pragma unroll
        for (int mb = 0; mb < 4; mb++)
#pragma unroll
            for (int nb = 0; nb < 8; nb++) {
                const float* a = acc[mb][nb];
                int m = mw + mb * 16 + g;
                int k = nw + nb * 8 + 2 * tt;
                *(unsigned*)(Cf + pkoff(z, m,     k)) = packh2(a[0] * sc, a[1] * sc);
                *(unsigned*)(Cf + pkoff(z, m + 8, k)) = packh2(a[2] * sc, a[3] * sc);
            }
    } else {
        __half* Xh = (__half*)g_Xh4;
        const float sc = SCALE / 256.f;
        const size_t zoff = (size_t)z << 20;
#pragma unroll
        for (int mb = 0; mb < 4; mb++)
#pragma unroll
            for (int nb = 0; nb < 8; nb++) {
                const float* a = acc[mb][nb];
                size_t base = zoff + (size_t)(mw + mb * 16 + g) * 1024 + nw + nb * 8 + 2 * tt;
                *(unsigned*)&Xh[base]            = packh2(a[0] * sc, a[1] * sc);
                *(unsigned*)&Xh[base + 8 * 1024] = packh2(a[2] * sc, a[3] * sc);
            }
    }
}

// ============================================================
// Kernel 4: output projection PARTIALS (X read as f16).
// Yp[b][cg][o][n] = sum_{c in cg-chunk} X[b,c,n]*w_out[o,c]
// grid (32 nt, 4 b, 8 cg), block 256 (32 n x 8 og of 4 outputs).
// ============================================================
__global__ __launch_bounds__(256) void proj_kernel(const float* __restrict__ wout) {
    __shared__ float ws[32][64];
    const int b  = blockIdx.y;
    const int cg = blockIdx.z;
    const int n  = blockIdx.x * 32 + (threadIdx.x & 31);
    const int og = threadIdx.x >> 5;
    const __half* X = (const __half*)g_Xh4 + ((size_t)b << 22);

    float acc[4] = {0.f, 0.f, 0.f, 0.f};

    for (int c0 = cg * 512; c0 < cg * 512 + 512; c0 += 64) {
        __syncthreads();
#pragma unroll
        for (int i = 0; i < 2; i++) {
            int idx = threadIdx.x + 256 * i;
            int o = idx >> 4, c4 = (idx & 15) << 2;
            *(float4*)&ws[o][c4] = *(const float4*)&wout[(size_t)o * 4096 + c0 + c4];
        }
        __syncthreads();
#pragma unroll 16
        for (int cl = 0; cl < 64; cl++) {
            float x = __half2float(X[(size_t)(c0 + cl) * 1024 + n]);
#pragma unroll
            for (int j = 0; j < 4; j++) acc[j] += ws[og * 4 + j][cl] * x;
        }
    }
#pragma unroll
    for (int j = 0; j < 4; j++)
        g_Yp[(((size_t)b * 8 + cg) * 32 + og * 4 + j) * 1024 + n] = acc[j];
}

// ============================================================
// Kernel 5: finalize — Y = bias + sum_cg Yp; per-(b,og) stat partials.
// grid (16): b = bx>>2, og = bx&3 (8 o each). block 1024 (one n per thread).
// ============================================================
__global__ __launch_bounds__(1024) void finalize_kernel(const float* __restrict__ bout) {
    __shared__ float ss[32], ss2[32];
    const int b  = blockIdx.x >> 2;
    const int og = blockIdx.x & 3;
    const int t  = threadIdx.x;   // n
    const float* Yp = g_Yp + (size_t)b * 8 * 32 * 1024;

    float s = 0.f, s2 = 0.f;
#pragma unroll
    for (int oo = 0; oo < 8; oo++) {
        int o = og * 8 + oo;
        float y = bout[o];
#pragma unroll
        for (int cgi = 0; cgi < 8; cgi++)
            y += Yp[((size_t)cgi * 32 + o) * 1024 + t];
        g_Y[((size_t)b * 32 + o) * 1024 + t] = y;
        s += y; s2 += y * y;
    }
#pragma unroll
    for (int o = 16; o; o >>= 1) {
        s  += __shfl_xor_sync(0xffffffffu, s, o);
        s2 += __shfl_xor_sync(0xffffffffu, s2, o);
    }
    if ((t & 31) == 0) { ss[t >> 5] = s; ss2[t >> 5] = s2; }
    __syncthreads();
    if (t < 32) {
        s = ss[t]; s2 = ss2[t];
#pragma unroll
        for (int o = 16; o; o >>= 1) {
            s  += __shfl_xor_sync(0xffffffffu, s, o);
            s2 += __shfl_xor_sync(0xffffffffu, s2, o);
        }
        if (t == 0) {
            g_pst[(b * 4 + og) * 2]     = s;
            g_pst[(b * 4 + og) * 2 + 1] = s2;
        }
    }
}

// ============================================================
// Kernel 6: GroupNorm finalize -> d_out.
// ============================================================
__global__ void gn_kernel(const float* __restrict__ gamma,
                          const float* __restrict__ beta,
                          float* __restrict__ out) {
    int idx = blockIdx.x * 256 + threadIdx.x;
    int b = idx >> 15;
    int o = (idx >> 10) & 31;
    float s  = g_pst[b * 8]     + g_pst[b * 8 + 2] + g_pst[b * 8 + 4] + g_pst[b * 8 + 6];
    float s2 = g_pst[b * 8 + 1] + g_pst[b * 8 + 3] + g_pst[b * 8 + 5] + g_pst[b * 8 + 7];
    float mean = s * (1.f / 32768.f);
    float var  = s2 * (1.f / 32768.f) - mean * mean;
    float rstd = rsqrtf(var + EPSGN);
    out[idx] = (g_Y[idx] - mean) * rstd * gamma[o] + beta[o];
}

// ============================================================
extern "C" void kernel_launch(void* const* d_in, const int* in_sizes, int n_in,
                              void* d_out, int out_size) {
    (void)in_sizes; (void)n_in; (void)out_size;
    const float* image = (const float*)d_in[0];
    const float* w_qkv = (const float*)d_in[1];
    const float* b_qkv = (const float*)d_in[2];
    const float* w_out = (const float*)d_in[3];
    const float* b_out = (const float*)d_in[4];
    const float* gamma = (const float*)d_in[5];
    const float* beta  = (const float*)d_in[6];
    float* out = (float*)d_out;

    cudaFuncSetAttribute(gemm_mma_kernel,
                         cudaFuncAttributeMaxDynamicSharedMemorySize, GEMM_SMEM);

    qkv_kernel<<<dim3(8, 192, 4), 256>>>(image, w_qkv, b_qkv);        // 1
    ksm_q_kernel<<<dim3(32, 16, 2), 1024>>>();                        // 2
    gemm_mma_kernel<<<dim3(8, 4, 16), 256, GEMM_SMEM>>>(0);           // 3
    gemm_mma_kernel<<<dim3(8, 4, 16), 256, GEMM_SMEM>>>(1);           // 4 (profiled)
    proj_kernel<<<dim3(32, 4, 8), 256>>>(w_out);                      // 5
    finalize_kernel<<<16, 1024>>>(b_out);                             // 6
    gn_kernel<<<512, 256>>>(gamma, beta, out);                        // 7
}

// round 15
// speedup vs baseline: 2.0956x; 1.0904x over previous
#include <cuda_runtime.h>
#include <cuda_fp16.h>
#include <math.h>
#include <stdint.h>

// ---------------- problem constants ----------------
#define NB    4
#define NC    32
#define NSP   1024
#define ND    1024
#define NBH   16
#define SCALE 0.17677669529663687f   // 1/sqrt(32)
#define EPSGN 1e-5f
#define LOG2E 1.4426950408889634f

// ---------------- scratch (device globals; allocation-free) ----------------
__device__ float g_Y  [NB * NC * NSP];        // projection out, pre-GN
__device__ float g_Yp [NB * 8 * NC * NSP];    // proj partials [b][cg][o][n]
__device__ float g_pst[NB * 4 * 2];           // per-(b,og) partial {sum, sumsq}

#define HFN (NBH * ND * NSP / 8)
// natural f16 [z][d][n]:
__device__ uint4 g_QH4[HFN];   // q pre-softmax f16
__device__ uint4 g_KH4[HFN];   // k pre-softmax f16
__device__ uint4 g_Xh4[HFN];   // attention out [z][e][n] f16
// TILE-PACKED + PRE-SWIZZLED f16 (blocks of 8192B = 128 rows x 64B):
__device__ uint4 g_Vf4[HFN];   // v  [e][n]
__device__ uint4 g_Kf4[HFN];   // 256*k-softmax [d][n]
__device__ uint4 g_Qf4[HFN];   // 256*q-softmax^T [n][d]
__device__ uint4 g_Cf4[HFN];   // ctx^T [e][d]

// ---------------- small helpers ----------------
__device__ __forceinline__ uint32_t smem_u32(const void* p) {
    uint32_t a;
    asm("{ .reg .u64 t; cvta.to.shared.u64 t, %1; cvt.u32.u64 %0, t; }" : "=r"(a) : "l"(p));
    return a;
}
__device__ __forceinline__ unsigned packh2(float a, float b) {
    __half2 p = __floats2half2_rn(a, b);
    return *reinterpret_cast<unsigned*>(&p);
}
// polynomial exp2 on the FMA pipe (rel err ~4e-5); t clamped to [-120, 120]
__device__ __forceinline__ float pexp2(float t) {
    t = fmaxf(t, -120.f);
    int i = __float2int_rn(t);
    float f = t - (float)i;
    float p = fmaf(f, 0.0096181f, 0.0555041f);
    p = fmaf(f, p, 0.2402265f);
    p = fmaf(f, p, 0.6931472f);
    p = fmaf(f, p, 1.0f);
    return p * __int_as_float((i + 127) << 23);
}
// byte offset of element (row, k) of matrix z in packed-swizzled layout
__device__ __forceinline__ size_t pkoff(int z, int row, int k) {
    size_t blk = (size_t)(z * 8 + (row >> 7)) * 32 + (k >> 5);
    int r = row & 127, kk = k & 31;
    return blk * 8192 +
           (uint32_t)(r * 64 + ((((kk >> 3) + (r >> 1)) & 3) << 4) + (kk & 7) * 2);
}
__device__ __forceinline__ uint32_t swzoff(int R, int ch) {
    return (uint32_t)(R * 64 + (((ch + (R >> 1)) & 3) << 4));
}
__device__ __forceinline__ void mbar_init(uint32_t a, uint32_t cnt) {
    asm volatile("mbarrier.init.shared.b64 [%0], %1;" :: "r"(a), "r"(cnt) : "memory");
}
__device__ __forceinline__ void mbar_expect_tx(uint32_t a, uint32_t tx) {
    asm volatile("mbarrier.arrive.expect_tx.shared.b64 _, [%0], %1;"
                 :: "r"(a), "r"(tx) : "memory");
}
__device__ __forceinline__ void mbar_arrive(uint32_t a) {
    asm volatile("mbarrier.arrive.shared.b64 _, [%0];" :: "r"(a) : "memory");
}
__device__ __forceinline__ void mbar_wait(uint32_t a, uint32_t phase) {
    asm volatile(
        "{\n\t.reg .pred P;\n"
        "W%=:\n\t"
        "mbarrier.try_wait.parity.shared::cta.b64 P, [%0], %1;\n\t"
        "@!P bra W%=;\n\t}"
        :: "r"(a), "r"(phase) : "memory");
}
__device__ __forceinline__ void mbar_wait_acq(uint32_t a, uint32_t phase) {
    asm volatile(
        "{\n\t.reg .pred P;\n"
        "W%=:\n\t"
        "mbarrier.try_wait.parity.acquire.cta.shared::cta.b64 P, [%0], %1;\n\t"
        "@!P bra W%=;\n\t}"
        :: "r"(a), "r"(phase) : "memory");
}
__device__ __forceinline__ void bulkcp(uint32_t sdst, const void* gsrc,
                                       uint32_t bytes, uint32_t mb) {
    asm volatile(
        "cp.async.bulk.shared::cta.global.mbarrier::complete_tx::bytes [%0], [%1], %2, [%3];"
        :: "r"(sdst), "l"(gsrc), "r"(bytes), "r"(mb) : "memory");
}
__device__ __forceinline__ void ldsm4(unsigned* r, uint32_t addr) {
    asm volatile("ldmatrix.sync.aligned.m8n8.x4.shared.b16 {%0,%1,%2,%3}, [%4];"
                 : "=r"(r[0]), "=r"(r[1]), "=r"(r[2]), "=r"(r[3]) : "r"(addr));
}
__device__ __forceinline__ void mma16816(float* c, const unsigned* a, const unsigned* b) {
    asm volatile(
        "mma.sync.aligned.m16n8k16.row.col.f32.f16.f16.f32 "
        "{%0,%1,%2,%3}, {%4,%5,%6,%7}, {%8,%9}, {%0,%1,%2,%3};"
        : "+f"(c[0]), "+f"(c[1]), "+f"(c[2]), "+f"(c[3])
        : "r"(a[0]), "r"(a[1]), "r"(a[2]), "r"(a[3]), "r"(b[0]), "r"(b[1]));
}

// ============================================================
// Kernel 1: QKV projection. q,k -> f16 natural [d][n]; v -> f16 packed.
// ============================================================
__global__ __launch_bounds__(256) void qkv_kernel(const float* __restrict__ img,
                                                  const float* __restrict__ w,
                                                  const float* __restrict__ bias) {
    __shared__ float xs[32][128];
    __shared__ float ws[64][32];
    __shared__ float bs[64];

    const int b  = blockIdx.z;
    const int o0 = blockIdx.y * 64;
    const int n0 = blockIdx.x * 128;
    const int t  = threadIdx.x;

#pragma unroll
    for (int i = 0; i < 4; i++) {
        int idx = t + 256 * i;
        int c = idx >> 5, c4 = (idx & 31) << 2;
        *(float4*)&xs[c][c4] = *(const float4*)&img[((size_t)b * 32 + c) * 1024 + n0 + c4];
    }
#pragma unroll
    for (int i = 0; i < 2; i++) {
        int idx = t + 256 * i;
        int o = idx >> 3, c4 = (idx & 7) << 2;
        *(float4*)&ws[o][c4] = *(const float4*)&w[(size_t)(o0 + o) * 32 + c4];
    }
    if (t < 64) bs[t] = bias[o0 + t];
    __syncthreads();

    const int tx = t & 31;
    const int oy = t >> 5;

    float acc[8][4];
#pragma unroll
    for (int r = 0; r < 8; r++) {
        float bv = bs[8 * oy + r];
#pragma unroll
        for (int i = 0; i < 4; i++) acc[r][i] = bv;
    }
#pragma unroll
    for (int c = 0; c < 32; c++) {
        float4 x = *(const float4*)&xs[c][4 * tx];
#pragma unroll
        for (int r = 0; r < 8; r++) {
            float wv = ws[8 * oy + r][c];
            acc[r][0] += wv * x.x; acc[r][1] += wv * x.y;
            acc[r][2] += wv * x.z; acc[r][3] += wv * x.w;
        }
    }

    const int nglob = n0 + 4 * tx;
#pragma unroll
    for (int r = 0; r < 8; r++) {
        int o     = o0 + 8 * oy + r;
        int which = o >> 12;
        int oc    = o & 4095;
        int h     = oc & 3;
        int cch   = oc >> 2;
        int zz    = b * 4 + h;
        uint2 hv;
        hv.x = packh2(acc[r][0], acc[r][1]);
        hv.y = packh2(acc[r][2], acc[r][3]);
        if (which == 2) {
            *(uint2*)((char*)g_Vf4 + pkoff(zz, cch, nglob)) = hv;
        } else {
            __half* dst = (which == 0) ? (__half*)g_QH4 : (__half*)g_KH4;
            *(uint2*)&dst[((size_t)zz << 20) + (size_t)cch * 1024 + nglob] = hv;
        }
    }
}

// ============================================================
// Kernel 2 (fused dual-role), dual-pipe exp (MUFU + FMA poly):
// z-slice 0 -> k softmax over n (x256, f16 packed [d][n]);
// z-slice 1 -> q: denominator + softmax-apply (x256) + transpose -> qT[n][d].
// grid (32, 16, 2), block 1024.
// ============================================================
__global__ __launch_bounds__(1024) void ksm_q_kernel() {
    const int z = blockIdx.y;
    if (blockIdx.z == 0) {
        const int lane = threadIdx.x & 31;
        const int w    = threadIdx.x >> 5;
        const int d    = blockIdx.x * 32 + w;
        const __half2* src =
            (const __half2*)((const __half*)g_KH4 + ((size_t)z << 20) + (size_t)d * 1024);

        float2 vals[16];
        float m = -3.402823466e38f;
#pragma unroll
        for (int j = 0; j < 16; j++) {
            __half2 h = src[j * 32 + lane];
            vals[j] = __half22float2(h);
            m = fmaxf(m, fmaxf(vals[j].x, vals[j].y));
        }
#pragma unroll
        for (int o = 16; o; o >>= 1) m = fmaxf(m, __shfl_xor_sync(0xffffffffu, m, o));
        float s = 0.f;
#pragma unroll
        for (int j = 0; j < 16; j++) {
            vals[j].x = __expf(vals[j].x - m);                 // MUFU pipe
            vals[j].y = pexp2((vals[j].y - m) * LOG2E);        // FMA pipe
            s += vals[j].x + vals[j].y;
        }
#pragma unroll
        for (int o = 16; o; o >>= 1) s += __shfl_xor_sync(0xffffffffu, s, o);
        float inv = 256.f / s;

        char* KfB = (char*)g_Kf4;
#pragma unroll
        for (int j = 0; j < 16; j++) {
            unsigned u = packh2(vals[j].x * inv, vals[j].y * inv);
            *(unsigned*)(KfB + pkoff(z, d, j * 64 + 2 * lane)) = u;
        }
    } else {
        __shared__ float red[32][32];
        __shared__ float rinv[32];
        const int nl = threadIdx.x & 31;
        const int dg = threadIdx.x >> 5;
        const int n  = blockIdx.x * 32 + nl;
        const __half* src = (const __half*)g_QH4 + ((size_t)z << 20) + n;

        float vals[32];
        float s = 0.f;
#pragma unroll
        for (int j = 0; j < 32; j += 2) {
            float x0 = __half2float(src[(size_t)(dg * 32 + j) * 1024]);
            float x1 = __half2float(src[(size_t)(dg * 32 + j + 1) * 1024]);
            vals[j]     = __expf(x0);               // MUFU pipe
            vals[j + 1] = pexp2(x1 * LOG2E);        // FMA pipe
            s += vals[j] + vals[j + 1];
        }
        red[dg][nl] = s;
        __syncthreads();
        if (dg == 0) {
            float tot = 0.f;
#pragma unroll
            for (int r = 0; r < 32; r++) tot += red[r][nl];
            rinv[nl] = 256.f / tot;
        }
        __syncthreads();
        float inv = rinv[nl];

        char* QfB = (char*)g_Qf4;
#pragma unroll
        for (int g = 0; g < 4; g++) {
            uint4 u;
            u.x = packh2(vals[g * 8 + 0] * inv, vals[g * 8 + 1] * inv);
            u.y = packh2(vals[g * 8 + 2] * inv, vals[g * 8 + 3] * inv);
            u.z = packh2(vals[g * 8 + 4] * inv, vals[g * 8 + 5] * inv);
            u.w = packh2(vals[g * 8 + 6] * inv, vals[g * 8 + 7] * inv);
            *(uint4*)(QfB + pkoff(z, n, dg * 32 + g * 8)) = u;
        }
    }
}

// ============================================================
// Kernel 3: single-pass f16 TN GEMM, bulk-TMA + mma.sync, with
// full/empty mbarrier producer-consumer ring (NO syncthreads convoy):
//   full[s]  : tx-barrier, completed by TMA arrival
//   empty[s] : 8 warp-arrivals (lane 0 after that warp's LDSMs)
// CTA 256x128 (8 warps, warp tile 64x64), K chunk 32, NSTAGE=4 x 24KB.
// grid (8 nt, 4 mt, 16 z), block 256.
// ============================================================
#define STAGE_BYTES 24576
#define NSTAGE 4
#define GEMM_SMEM (NSTAGE * STAGE_BYTES + 128)

__global__ __launch_bounds__(256, 1) void gemm_mma_kernel(int stage) {
    extern __shared__ char smem[];
    const uint32_t sbase  = smem_u32(smem);
    const uint32_t mfull  = sbase + NSTAGE * STAGE_BYTES;
    const uint32_t mempty = mfull + 32;
    const int t    = threadIdx.x;
    const int lane = t & 31;
    const int wid  = t >> 5;

    const char *A, *B;
    if (stage == 0) { A = (const char*)g_Vf4; B = (const char*)g_Kf4; }
    else            { A = (const char*)g_Cf4; B = (const char*)g_Qf4; }
    const int z  = blockIdx.z;
    const int mt = blockIdx.y;
    const int nt = blockIdx.x;
    const char* gA0 = A + (size_t)(z * 8 + 2 * mt)     * 32 * 8192;
    const char* gA1 = A + (size_t)(z * 8 + 2 * mt + 1) * 32 * 8192;
    const char* gB  = B + (size_t)(z * 8 + nt)         * 32 * 8192;

    if (t == 0) {
#pragma unroll
        for (int s = 0; s < NSTAGE; s++) {
            mbar_init(mfull  + 8 * s, 1);
            mbar_init(mempty + 8 * s, 8);
        }
        asm volatile("fence.proxy.async.shared::cta;" ::: "memory");
    }
    __syncthreads();

    auto issue = [&](int j) {
        const int st = j & (NSTAGE - 1);
        const uint32_t mb = mfull + 8 * st;
        const uint32_t sb = sbase + st * STAGE_BYTES;
        mbar_expect_tx(mb, STAGE_BYTES);
        bulkcp(sb,         gA0 + (size_t)j * 8192, 8192, mb);
        bulkcp(sb + 8192,  gA1 + (size_t)j * 8192, 8192, mb);
        bulkcp(sb + 16384, gB  + (size_t)j * 8192, 8192, mb);
    };
    if (t == 0) { issue(0); issue(1); issue(2); }

    const int wm = wid & 3;
    const int wn = wid >> 2;
    const int aRloc = (wm & 1) * 64 + (lane & 15);
    const int aHalf = wm >> 1;
    const int aHi   = lane >> 4;
    const int bR    = wn * 64 + (lane & 7) + ((lane >> 4) << 3);
    const int bHi   = (lane >> 3) & 1;

    float acc[4][8][4];
#pragma unroll
    for (int i = 0; i < 4; i++)
#pragma unroll
        for (int j = 0; j < 8; j++)
#pragma unroll
            for (int p = 0; p < 4; p++) acc[i][j][p] = 0.f;

#pragma unroll 1
    for (int kt = 0; kt < 32; kt++) {
        // consumer: every warp waits for its stage's data
        mbar_wait_acq(mfull + 8 * (kt & 3), (kt >> 2) & 1);

        const uint32_t sb = sbase + (kt & 3) * STAGE_BYTES;
        const uint32_t ab = sb + aHalf * 8192;
        const uint32_t bb = sb + 16384;

        unsigned a0[4][4], b0[4][4], a1[4][4], b1[4][4];
#pragma unroll
        for (int np = 0; np < 4; np++) {
            ldsm4(b0[np], bb + swzoff(bR + np * 16, bHi));
            ldsm4(b1[np], bb + swzoff(bR + np * 16, 2 + bHi));
        }
#pragma unroll
        for (int mb = 0; mb < 4; mb++) {
            ldsm4(a0[mb], ab + swzoff(aRloc + mb * 16, aHi));
            ldsm4(a1[mb], ab + swzoff(aRloc + mb * 16, 2 + aHi));
        }
        // this warp is done reading stage kt
        if (lane == 0) mbar_arrive(mempty + 8 * (kt & 3));

#pragma unroll
        for (int mb = 0; mb < 4; mb++)
#pragma unroll
            for (int nb = 0; nb < 8; nb++)
                mma16816(acc[mb][nb], a0[mb], &b0[nb >> 1][(nb & 1) * 2]);
#pragma unroll
        for (int mb = 0; mb < 4; mb++)
#pragma unroll
            for (int nb = 0; nb < 8; nb++)
                mma16816(acc[mb][nb], a1[mb], &b1[nb >> 1][(nb & 1) * 2]);

        // producer: refill stage (kt+3)&3 once all warps released it
        if (t == 0 && kt + 3 < 32) {
            int j = kt + 3;
            if (j >= NSTAGE) mbar_wait(mempty + 8 * (j & 3), ((j >> 2) + 1) & 1);
            issue(j);
        }
    }

    // ---- epilogue
    const int g  = lane >> 2;
    const int tt = lane & 3;
    const int mw = mt * 256 + wm * 64;
    const int nw = nt * 128 + wn * 64;

    if (stage == 0) {
        char* Cf = (char*)g_Cf4;
        const float sc = 1.f / 256.f;
#pragma unroll
        for (int mb = 0; mb < 4; mb++)
#pragma unroll
            for (int nb = 0; nb < 8; nb++) {
                const float* a = acc[mb][nb];
                int m = mw + mb * 16 + g;
                int k = nw + nb * 8 + 2 * tt;
                *(unsigned*)(Cf + pkoff(z, m,     k)) = packh2(a[0] * sc, a[1] * sc);
                *(unsigned*)(Cf + pkoff(z, m + 8, k)) = packh2(a[2] * sc, a[3] * sc);
            }
    } else {
        __half* Xh = (__half*)g_Xh4;
        const float sc = SCALE / 256.f;
        const size_t zoff = (size_t)z << 20;
#pragma unroll
        for (int mb = 0; mb < 4; mb++)
#pragma unroll
            for (int nb = 0; nb < 8; nb++) {
                const float* a = acc[mb][nb];
                size_t base = zoff + (size_t)(mw + mb * 16 + g) * 1024 + nw + nb * 8 + 2 * tt;
                *(unsigned*)&Xh[base]            = packh2(a[0] * sc, a[1] * sc);
                *(unsigned*)&Xh[base + 8 * 1024] = packh2(a[2] * sc, a[3] * sc);
            }
    }
}

// ============================================================
// Kernel 4: output projection PARTIALS (X read as f16).
// grid (32 nt, 4 b, 8 cg), block 256 (32 n x 8 og of 4 outputs).
// ============================================================
__global__ __launch_bounds__(256) void proj_kernel(const float* __restrict__ wout) {
    __shared__ float ws[32][64];
    const int b  = blockIdx.y;
    const int cg = blockIdx.z;
    const int n  = blockIdx.x * 32 + (threadIdx.x & 31);
    const int og = threadIdx.x >> 5;
    const __half* X = (const __half*)g_Xh4 + ((size_t)b << 22);

    float acc[4] = {0.f, 0.f, 0.f, 0.f};

    for (int c0 = cg * 512; c0 < cg * 512 + 512; c0 += 64) {
        __syncthreads();
#pragma unroll
        for (int i = 0; i < 2; i++) {
            int idx = threadIdx.x + 256 * i;
            int o = idx >> 4, c4 = (idx & 15) << 2;
            *(float4*)&ws[o][c4] = *(const float4*)&wout[(size_t)o * 4096 + c0 + c4];
        }
        __syncthreads();
#pragma unroll 16
        for (int cl = 0; cl < 64; cl++) {
            float x = __half2float(X[(size_t)(c0 + cl) * 1024 + n]);
#pragma unroll
            for (int j = 0; j < 4; j++) acc[j] += ws[og * 4 + j][cl] * x;
        }
    }
#pragma unroll
    for (int j = 0; j < 4; j++)
        g_Yp[(((size_t)b * 8 + cg) * 32 + og * 4 + j) * 1024 + n] = acc[j];
}

// ============================================================
// Kernel 5: finalize — Y = bias + sum_cg Yp; per-(b,og) stat partials.
// ============================================================
__global__ __launch_bounds__(1024) void finalize_kernel(const float* __restrict__ bout) {
    __shared__ float ss[32], ss2[32];
    const int b  = blockIdx.x >> 2;
    const int og = blockIdx.x & 3;
    const int t  = threadIdx.x;   // n
    const float* Yp = g_Yp + (size_t)b * 8 * 32 * 1024;

    float s = 0.f, s2 = 0.f;
#pragma unroll
    for (int oo = 0; oo < 8; oo++) {
        int o = og * 8 + oo;
        float y = bout[o];
#pragma unroll
        for (int cgi = 0; cgi < 8; cgi++)
            y += Yp[((size_t)cgi * 32 + o) * 1024 + t];
        g_Y[((size_t)b * 32 + o) * 1024 + t] = y;
        s += y; s2 += y * y;
    }
#pragma unroll
    for (int o = 16; o; o >>= 1) {
        s  += __shfl_xor_sync(0xffffffffu, s, o);
        s2 += __shfl_xor_sync(0xffffffffu, s2, o);
    }
    if ((t & 31) == 0) { ss[t >> 5] = s; ss2[t >> 5] = s2; }
    __syncthreads();
    if (t < 32) {
        s = ss[t]; s2 = ss2[t];
#pragma unroll
        for (int o = 16; o; o >>= 1) {
            s  += __shfl_xor_sync(0xffffffffu, s, o);
            s2 += __shfl_xor_sync(0xffffffffu, s2, o);
        }
        if (t == 0) {
            g_pst[(b * 4 + og) * 2]     = s;
            g_pst[(b * 4 + og) * 2 + 1] = s2;
        }
    }
}

// ============================================================
// Kernel 6: GroupNorm finalize -> d_out.
// ============================================================
__global__ void gn_kernel(const float* __restrict__ gamma,
                          const float* __restrict__ beta,
                          float* __restrict__ out) {
    int idx = blockIdx.x * 256 + threadIdx.x;
    int b = idx >> 15;
    int o = (idx >> 10) & 31;
    float s  = g_pst[b * 8]     + g_pst[b * 8 + 2] + g_pst[b * 8 + 4] + g_pst[b * 8 + 6];
    float s2 = g_pst[b * 8 + 1] + g_pst[b * 8 + 3] + g_pst[b * 8 + 5] + g_pst[b * 8 + 7];
    float mean = s * (1.f / 32768.f);
    float var  = s2 * (1.f / 32768.f) - mean * mean;
    float rstd = rsqrtf(var + EPSGN);
    out[idx] = (g_Y[idx] - mean) * rstd * gamma[o] + beta[o];
}

// ============================================================
extern "C" void kernel_launch(void* const* d_in, const int* in_sizes, int n_in,
                              void* d_out, int out_size) {
    (void)in_sizes; (void)n_in; (void)out_size;
    const float* image = (const float*)d_in[0];
    const float* w_qkv = (const float*)d_in[1];
    const float* b_qkv = (const float*)d_in[2];
    const float* w_out = (const float*)d_in[3];
    const float* b_out = (const float*)d_in[4];
    const float* gamma = (const float*)d_in[5];
    const float* beta  = (const float*)d_in[6];
    float* out = (float*)d_out;

    cudaFuncSetAttribute(gemm_mma_kernel,
                         cudaFuncAttributeMaxDynamicSharedMemorySize, GEMM_SMEM);

    qkv_kernel<<<dim3(8, 192, 4), 256>>>(image, w_qkv, b_qkv);        // 1
    ksm_q_kernel<<<dim3(32, 16, 2), 1024>>>();                        // 2
    gemm_mma_kernel<<<dim3(8, 4, 16), 256, GEMM_SMEM>>>(0);           // 3
    gemm_mma_kernel<<<dim3(8, 4, 16), 256, GEMM_SMEM>>>(1);           // 4 (profiled)
    proj_kernel<<<dim3(32, 4, 8), 256>>>(w_out);                      // 5
    finalize_kernel<<<16, 1024>>>(b_out);                             // 6
    gn_kernel<<<512, 256>>>(gamma, beta, out);                        // 7
}

// round 16
// speedup vs baseline: 2.3068x; 1.1008x over previous
#include <cuda_runtime.h>
#include <cuda_fp16.h>
#include <math.h>
#include <stdint.h>

// ---------------- problem constants ----------------
#define NB    4
#define NC    32
#define NSP   1024
#define ND    1024
#define NBH   16
#define SCALE 0.17677669529663687f   // 1/sqrt(32)
#define EPSGN 1e-5f
#define LOG2E 1.4426950408889634f

// ---------------- scratch (device globals; allocation-free) ----------------
__device__ float g_Yp [NB * 8 * NC * NSP];    // proj partials [b][cg][o][n]
__device__ float g_pst[NB * 4 * 2];           // per-(b,og) partial {sum, sumsq}

#define HFN (NBH * ND * NSP / 8)
// natural f16 [z][d][n]:
__device__ uint4 g_QH4[HFN];   // q pre-softmax f16
__device__ uint4 g_KH4[HFN];   // k pre-softmax f16
__device__ uint4 g_Xh4[HFN];   // attention out [z][e][n] f16
// TILE-PACKED + PRE-SWIZZLED f16 (blocks of 8192B = 128 rows x 64B):
__device__ uint4 g_Vf4[HFN];   // v  [e][n]
__device__ uint4 g_Kf4[HFN];   // 256*k-softmax [d][n]
__device__ uint4 g_Qf4[HFN];   // 256*q-softmax^T [n][d]
__device__ uint4 g_Cf4[HFN];   // ctx^T [e][d]

// ---------------- small helpers ----------------
__device__ __forceinline__ uint32_t smem_u32(const void* p) {
    uint32_t a;
    asm("{ .reg .u64 t; cvta.to.shared.u64 t, %1; cvt.u32.u64 %0, t; }" : "=r"(a) : "l"(p));
    return a;
}
__device__ __forceinline__ unsigned packh2(float a, float b) {
    __half2 p = __floats2half2_rn(a, b);
    return *reinterpret_cast<unsigned*>(&p);
}
// polynomial exp2 on the FMA pipe (rel err ~4e-5)
__device__ __forceinline__ float pexp2(float t) {
    t = fmaxf(t, -120.f);
    int i = __float2int_rn(t);
    float f = t - (float)i;
    float p = fmaf(f, 0.0096181f, 0.0555041f);
    p = fmaf(f, p, 0.2402265f);
    p = fmaf(f, p, 0.6931472f);
    p = fmaf(f, p, 1.0f);
    return p * __int_as_float((i + 127) << 23);
}
// byte offset of element (row, k) of matrix z in packed-swizzled layout
__device__ __forceinline__ size_t pkoff(int z, int row, int k) {
    size_t blk = (size_t)(z * 8 + (row >> 7)) * 32 + (k >> 5);
    int r = row & 127, kk = k & 31;
    return blk * 8192 +
           (uint32_t)(r * 64 + ((((kk >> 3) + (r >> 1)) & 3) << 4) + (kk & 7) * 2);
}
__device__ __forceinline__ uint32_t swzoff(int R, int ch) {
    return (uint32_t)(R * 64 + (((ch + (R >> 1)) & 3) << 4));
}
__device__ __forceinline__ void mbar_init(uint32_t a, uint32_t cnt) {
    asm volatile("mbarrier.init.shared.b64 [%0], %1;" :: "r"(a), "r"(cnt) : "memory");
}
__device__ __forceinline__ void mbar_expect_tx(uint32_t a, uint32_t tx) {
    asm volatile("mbarrier.arrive.expect_tx.shared.b64 _, [%0], %1;"
                 :: "r"(a), "r"(tx) : "memory");
}
__device__ __forceinline__ void mbar_arrive(uint32_t a) {
    asm volatile("mbarrier.arrive.shared.b64 _, [%0];" :: "r"(a) : "memory");
}
__device__ __forceinline__ void mbar_wait(uint32_t a, uint32_t phase) {
    asm volatile(
        "{\n\t.reg .pred P;\n"
        "W%=:\n\t"
        "mbarrier.try_wait.parity.shared::cta.b64 P, [%0], %1;\n\t"
        "@!P bra W%=;\n\t}"
        :: "r"(a), "r"(phase) : "memory");
}
__device__ __forceinline__ void mbar_wait_acq(uint32_t a, uint32_t phase) {
    asm volatile(
        "{\n\t.reg .pred P;\n"
        "W%=:\n\t"
        "mbarrier.try_wait.parity.acquire.cta.shared::cta.b64 P, [%0], %1;\n\t"
        "@!P bra W%=;\n\t}"
        :: "r"(a), "r"(phase) : "memory");
}
__device__ __forceinline__ void bulkcp(uint32_t sdst, const void* gsrc,
                                       uint32_t bytes, uint32_t mb) {
    asm volatile(
        "cp.async.bulk.shared::cta.global.mbarrier::complete_tx::bytes [%0], [%1], %2, [%3];"
        :: "r"(sdst), "l"(gsrc), "r"(bytes), "r"(mb) : "memory");
}
__device__ __forceinline__ void ldsm4(unsigned* r, uint32_t addr) {
    asm volatile("ldmatrix.sync.aligned.m8n8.x4.shared.b16 {%0,%1,%2,%3}, [%4];"
                 : "=r"(r[0]), "=r"(r[1]), "=r"(r[2]), "=r"(r[3]) : "r"(addr));
}
__device__ __forceinline__ void mma16816(float* c, const unsigned* a, const unsigned* b) {
    asm volatile(
        "mma.sync.aligned.m16n8k16.row.col.f32.f16.f16.f32 "
        "{%0,%1,%2,%3}, {%4,%5,%6,%7}, {%8,%9}, {%0,%1,%2,%3};"
        : "+f"(c[0]), "+f"(c[1]), "+f"(c[2]), "+f"(c[3])
        : "r"(a[0]), "r"(a[1]), "r"(a[2]), "r"(a[3]), "r"(b[0]), "r"(b[1]));
}

// ============================================================
// Kernel 1: QKV projection. q,k -> f16 natural [d][n]; v -> f16 packed.
// ============================================================
__global__ __launch_bounds__(256) void qkv_kernel(const float* __restrict__ img,
                                                  const float* __restrict__ w,
                                                  const float* __restrict__ bias) {
    __shared__ float xs[32][128];
    __shared__ float ws[64][32];
    __shared__ float bs[64];

    const int b  = blockIdx.z;
    const int o0 = blockIdx.y * 64;
    const int n0 = blockIdx.x * 128;
    const int t  = threadIdx.x;

#pragma unroll
    for (int i = 0; i < 4; i++) {
        int idx = t + 256 * i;
        int c = idx >> 5, c4 = (idx & 31) << 2;
        *(float4*)&xs[c][c4] = *(const float4*)&img[((size_t)b * 32 + c) * 1024 + n0 + c4];
    }
#pragma unroll
    for (int i = 0; i < 2; i++) {
        int idx = t + 256 * i;
        int o = idx >> 3, c4 = (idx & 7) << 2;
        *(float4*)&ws[o][c4] = *(const float4*)&w[(size_t)(o0 + o) * 32 + c4];
    }
    if (t < 64) bs[t] = bias[o0 + t];
    __syncthreads();

    const int tx = t & 31;
    const int oy = t >> 5;

    float acc[8][4];
#pragma unroll
    for (int r = 0; r < 8; r++) {
        float bv = bs[8 * oy + r];
#pragma unroll
        for (int i = 0; i < 4; i++) acc[r][i] = bv;
    }
#pragma unroll
    for (int c = 0; c < 32; c++) {
        float4 x = *(const float4*)&xs[c][4 * tx];
#pragma unroll
        for (int r = 0; r < 8; r++) {
            float wv = ws[8 * oy + r][c];
            acc[r][0] += wv * x.x; acc[r][1] += wv * x.y;
            acc[r][2] += wv * x.z; acc[r][3] += wv * x.w;
        }
    }

    const int nglob = n0 + 4 * tx;
#pragma unroll
    for (int r = 0; r < 8; r++) {
        int o     = o0 + 8 * oy + r;
        int which = o >> 12;
        int oc    = o & 4095;
        int h     = oc & 3;
        int cch   = oc >> 2;
        int zz    = b * 4 + h;
        uint2 hv;
        hv.x = packh2(acc[r][0], acc[r][1]);
        hv.y = packh2(acc[r][2], acc[r][3]);
        if (which == 2) {
            *(uint2*)((char*)g_Vf4 + pkoff(zz, cch, nglob)) = hv;
        } else {
            __half* dst = (which == 0) ? (__half*)g_QH4 : (__half*)g_KH4;
            *(uint2*)&dst[((size_t)zz << 20) + (size_t)cch * 1024 + nglob] = hv;
        }
    }
}

// ============================================================
// Kernel 2 (fused dual-role), dual-pipe exp (MUFU + FMA poly):
// z-slice 0 -> k softmax over n (x256, f16 packed [d][n]);
// z-slice 1 -> q: denominator + softmax-apply (x256) + transpose -> qT[n][d].
// grid (32, 16, 2), block 1024.
// ============================================================
__global__ __launch_bounds__(1024) void ksm_q_kernel() {
    const int z = blockIdx.y;
    if (blockIdx.z == 0) {
        const int lane = threadIdx.x & 31;
        const int w    = threadIdx.x >> 5;
        const int d    = blockIdx.x * 32 + w;
        const __half2* src =
            (const __half2*)((const __half*)g_KH4 + ((size_t)z << 20) + (size_t)d * 1024);

        float2 vals[16];
        float m = -3.402823466e38f;
#pragma unroll
        for (int j = 0; j < 16; j++) {
            __half2 h = src[j * 32 + lane];
            vals[j] = __half22float2(h);
            m = fmaxf(m, fmaxf(vals[j].x, vals[j].y));
        }
#pragma unroll
        for (int o = 16; o; o >>= 1) m = fmaxf(m, __shfl_xor_sync(0xffffffffu, m, o));
        float s = 0.f;
#pragma unroll
        for (int j = 0; j < 16; j++) {
            vals[j].x = __expf(vals[j].x - m);
            vals[j].y = pexp2((vals[j].y - m) * LOG2E);
            s += vals[j].x + vals[j].y;
        }
#pragma unroll
        for (int o = 16; o; o >>= 1) s += __shfl_xor_sync(0xffffffffu, s, o);
        float inv = 256.f / s;

        char* KfB = (char*)g_Kf4;
#pragma unroll
        for (int j = 0; j < 16; j++) {
            unsigned u = packh2(vals[j].x * inv, vals[j].y * inv);
            *(unsigned*)(KfB + pkoff(z, d, j * 64 + 2 * lane)) = u;
        }
    } else {
        __shared__ float red[32][32];
        __shared__ float rinv[32];
        const int nl = threadIdx.x & 31;
        const int dg = threadIdx.x >> 5;
        const int n  = blockIdx.x * 32 + nl;
        const __half* src = (const __half*)g_QH4 + ((size_t)z << 20) + n;

        float vals[32];
        float s = 0.f;
#pragma unroll
        for (int j = 0; j < 32; j += 2) {
            float x0 = __half2float(src[(size_t)(dg * 32 + j) * 1024]);
            float x1 = __half2float(src[(size_t)(dg * 32 + j + 1) * 1024]);
            vals[j]     = __expf(x0);
            vals[j + 1] = pexp2(x1 * LOG2E);
            s += vals[j] + vals[j + 1];
        }
        red[dg][nl] = s;
        __syncthreads();
        if (dg == 0) {
            float tot = 0.f;
#pragma unroll
            for (int r = 0; r < 32; r++) tot += red[r][nl];
            rinv[nl] = 256.f / tot;
        }
        __syncthreads();
        float inv = rinv[nl];

        char* QfB = (char*)g_Qf4;
#pragma unroll
        for (int g = 0; g < 4; g++) {
            uint4 u;
            u.x = packh2(vals[g * 8 + 0] * inv, vals[g * 8 + 1] * inv);
            u.y = packh2(vals[g * 8 + 2] * inv, vals[g * 8 + 3] * inv);
            u.z = packh2(vals[g * 8 + 4] * inv, vals[g * 8 + 5] * inv);
            u.w = packh2(vals[g * 8 + 6] * inv, vals[g * 8 + 7] * inv);
            *(uint4*)(QfB + pkoff(z, n, dg * 32 + g * 8)) = u;
        }
    }
}

// ============================================================
// Kernel 3: single-pass f16 TN GEMM, bulk-TMA + mma.sync,
// full/empty mbarrier ring. 512 THREADS (16 warps, 4/SMSP for
// latency hiding), CTA 256x128, warp tile 64x32, K chunk 32,
// NSTAGE=4 x 24KB.  grid (8 nt, 4 mt, 16 z), block 512.
// ============================================================
#define STAGE_BYTES 24576
#define NSTAGE 4
#define GEMM_SMEM (NSTAGE * STAGE_BYTES + 128)

__global__ __launch_bounds__(512, 1) void gemm_mma_kernel(int stage) {
    extern __shared__ char smem[];
    const uint32_t sbase  = smem_u32(smem);
    const uint32_t mfull  = sbase + NSTAGE * STAGE_BYTES;
    const uint32_t mempty = mfull + 32;
    const int t    = threadIdx.x;
    const int lane = t & 31;
    const int wid  = t >> 5;

    const char *A, *B;
    if (stage == 0) { A = (const char*)g_Vf4; B = (const char*)g_Kf4; }
    else            { A = (const char*)g_Cf4; B = (const char*)g_Qf4; }
    const int z  = blockIdx.z;
    const int mt = blockIdx.y;
    const int nt = blockIdx.x;
    const char* gA0 = A + (size_t)(z * 8 + 2 * mt)     * 32 * 8192;
    const char* gA1 = A + (size_t)(z * 8 + 2 * mt + 1) * 32 * 8192;
    const char* gB  = B + (size_t)(z * 8 + nt)         * 32 * 8192;

    if (t == 0) {
#pragma unroll
        for (int s = 0; s < NSTAGE; s++) {
            mbar_init(mfull  + 8 * s, 1);
            mbar_init(mempty + 8 * s, 16);
        }
        asm volatile("fence.proxy.async.shared::cta;" ::: "memory");
    }
    __syncthreads();

    auto issue = [&](int j) {
        const int st = j & (NSTAGE - 1);
        const uint32_t mb = mfull + 8 * st;
        const uint32_t sb = sbase + st * STAGE_BYTES;
        mbar_expect_tx(mb, STAGE_BYTES);
        bulkcp(sb,         gA0 + (size_t)j * 8192, 8192, mb);
        bulkcp(sb + 8192,  gA1 + (size_t)j * 8192, 8192, mb);
        bulkcp(sb + 16384, gB  + (size_t)j * 8192, 8192, mb);
    };
    if (t == 0) { issue(0); issue(1); issue(2); }

    // warp tile 64x32: wm = wid&3 (m, 4x64 rows), wn = wid>>2 (n, 4x32 cols)
    const int wm = wid & 3;
    const int wn = wid >> 2;
    const int aRloc = (wm & 1) * 64 + (lane & 15);
    const int aHalf = wm >> 1;
    const int aHi   = lane >> 4;
    const int bR    = wn * 32 + (lane & 7) + ((lane >> 4) << 3);
    const int bHi   = (lane >> 3) & 1;

    float acc[4][4][4];
#pragma unroll
    for (int i = 0; i < 4; i++)
#pragma unroll
        for (int j = 0; j < 4; j++)
#pragma unroll
            for (int p = 0; p < 4; p++) acc[i][j][p] = 0.f;

#pragma unroll 1
    for (int kt = 0; kt < 32; kt++) {
        mbar_wait_acq(mfull + 8 * (kt & 3), (kt >> 2) & 1);

        const uint32_t sb = sbase + (kt & 3) * STAGE_BYTES;
        const uint32_t ab = sb + aHalf * 8192;
        const uint32_t bb = sb + 16384;

        // k16 #0
        unsigned af[4][4], bf[2][4];
#pragma unroll
        for (int np = 0; np < 2; np++)
            ldsm4(bf[np], bb + swzoff(bR + np * 16, bHi));
#pragma unroll
        for (int mb = 0; mb < 4; mb++)
            ldsm4(af[mb], ab + swzoff(aRloc + mb * 16, aHi));
#pragma unroll
        for (int mb = 0; mb < 4; mb++)
#pragma unroll
            for (int nb = 0; nb < 4; nb++)
                mma16816(acc[mb][nb], af[mb], &bf[nb >> 1][(nb & 1) * 2]);

        // k16 #1
#pragma unroll
        for (int np = 0; np < 2; np++)
            ldsm4(bf[np], bb + swzoff(bR + np * 16, 2 + bHi));
#pragma unroll
        for (int mb = 0; mb < 4; mb++)
            ldsm4(af[mb], ab + swzoff(aRloc + mb * 16, 2 + aHi));
        if (lane == 0) mbar_arrive(mempty + 8 * (kt & 3));   // all reads of stage done
#pragma unroll
        for (int mb = 0; mb < 4; mb++)
#pragma unroll
            for (int nb = 0; nb < 4; nb++)
                mma16816(acc[mb][nb], af[mb], &bf[nb >> 1][(nb & 1) * 2]);

        if (t == 0 && kt + 3 < 32) {
            int j = kt + 3;
            if (j >= NSTAGE) mbar_wait(mempty + 8 * (j & 3), ((j >> 2) + 1) & 1);
            issue(j);
        }
    }

    // ---- epilogue
    const int g  = lane >> 2;
    const int tt = lane & 3;
    const int mw = mt * 256 + wm * 64;
    const int nw = nt * 128 + wn * 32;

    if (stage == 0) {
        char* Cf = (char*)g_Cf4;
        const float sc = 1.f / 256.f;
#pragma unroll
        for (int mb = 0; mb < 4; mb++)
#pragma unroll
            for (int nb = 0; nb < 4; nb++) {
                const float* a = acc[mb][nb];
                int m = mw + mb * 16 + g;
                int k = nw + nb * 8 + 2 * tt;
                *(unsigned*)(Cf + pkoff(z, m,     k)) = packh2(a[0] * sc, a[1] * sc);
                *(unsigned*)(Cf + pkoff(z, m + 8, k)) = packh2(a[2] * sc, a[3] * sc);
            }
    } else {
        __half* Xh = (__half*)g_Xh4;
        const float sc = SCALE / 256.f;
        const size_t zoff = (size_t)z << 20;
#pragma unroll
        for (int mb = 0; mb < 4; mb++)
#pragma unroll
            for (int nb = 0; nb < 4; nb++) {
                const float* a = acc[mb][nb];
                size_t base = zoff + (size_t)(mw + mb * 16 + g) * 1024 + nw + nb * 8 + 2 * tt;
                *(unsigned*)&Xh[base]            = packh2(a[0] * sc, a[1] * sc);
                *(unsigned*)&Xh[base + 8 * 1024] = packh2(a[2] * sc, a[3] * sc);
            }
    }
}

// ============================================================
// Kernel 4: output projection PARTIALS, half2-vectorized X reads.
// Yp[b][cg][o][n] = sum_{c in cg-chunk} X[b,c,n]*w_out[o,c]
// grid (16 nt, 4 b, 8 cg), block 256 = 32 half2-lanes (64 n) x 8 og.
// ============================================================
__global__ __launch_bounds__(256) void proj_kernel(const float* __restrict__ wout) {
    __shared__ float ws[32][64];
    const int b   = blockIdx.y;
    const int cg  = blockIdx.z;
    const int nn  = blockIdx.x * 32 + (threadIdx.x & 31);  // half2 index
    const int og  = threadIdx.x >> 5;
    const __half2* X2 = (const __half2*)((const __half*)g_Xh4 + ((size_t)b << 22));

    float2 acc[4];
#pragma unroll
    for (int j = 0; j < 4; j++) acc[j] = make_float2(0.f, 0.f);

    for (int c0 = cg * 512; c0 < cg * 512 + 512; c0 += 64) {
        __syncthreads();
#pragma unroll
        for (int i = 0; i < 2; i++) {
            int idx = threadIdx.x + 256 * i;
            int o = idx >> 4, c4 = (idx & 15) << 2;
            *(float4*)&ws[o][c4] = *(const float4*)&wout[(size_t)o * 4096 + c0 + c4];
        }
        __syncthreads();
#pragma unroll 16
        for (int cl = 0; cl < 64; cl++) {
            float2 x = __half22float2(X2[(size_t)(c0 + cl) * 512 + nn]);
#pragma unroll
            for (int j = 0; j < 4; j++) {
                float w = ws[og * 4 + j][cl];
                acc[j].x += w * x.x;
                acc[j].y += w * x.y;
            }
        }
    }
#pragma unroll
    for (int j = 0; j < 4; j++)
        *(float2*)&g_Yp[(((size_t)b * 8 + cg) * 32 + og * 4 + j) * 1024 + 2 * nn] = acc[j];
}

// ============================================================
// Kernel 5: stats — per-(b,og) {sum, sumsq} of y = bias + sum_cg Yp.
// grid (16): b = bx>>2, og = bx&3 (8 o each). block 1024 (one n per thread).
// ============================================================
__global__ __launch_bounds__(1024) void stats_kernel(const float* __restrict__ bout) {
    __shared__ float ss[32], ss2[32];
    const int b  = blockIdx.x >> 2;
    const int og = blockIdx.x & 3;
    const int t  = threadIdx.x;
    const float* Yp = g_Yp + (size_t)b * 8 * 32 * 1024;

    float s = 0.f, s2 = 0.f;
#pragma unroll
    for (int oo = 0; oo < 8; oo++) {
        int o = og * 8 + oo;
        float y = bout[o];
#pragma unroll
        for (int cgi = 0; cgi < 8; cgi++)
            y += Yp[((size_t)cgi * 32 + o) * 1024 + t];
        s += y; s2 += y * y;
    }
#pragma unroll
    for (int o = 16; o; o >>= 1) {
        s  += __shfl_xor_sync(0xffffffffu, s, o);
        s2 += __shfl_xor_sync(0xffffffffu, s2, o);
    }
    if ((t & 31) == 0) { ss[t >> 5] = s; ss2[t >> 5] = s2; }
    __syncthreads();
    if (t < 32) {
        s = ss[t]; s2 = ss2[t];
#pragma unroll
        for (int o = 16; o; o >>= 1) {
            s  += __shfl_xor_sync(0xffffffffu, s, o);
            s2 += __shfl_xor_sync(0xffffffffu, s2, o);
        }
        if (t == 0) {
            g_pst[(b * 4 + og) * 2]     = s;
            g_pst[(b * 4 + og) * 2 + 1] = s2;
        }
    }
}

// ============================================================
// Kernel 6: GroupNorm finalize -> d_out (recomputes y from Yp).
// ============================================================
__global__ void gn_kernel(const float* __restrict__ bout,
                          const float* __restrict__ gamma,
                          const float* __restrict__ beta,
                          float* __restrict__ out) {
    int idx = blockIdx.x * 256 + threadIdx.x;
    int b = idx >> 15;
    int o = (idx >> 10) & 31;
    int n = idx & 1023;
    const float* Yp = g_Yp + (size_t)b * 8 * 32 * 1024;
    float y = bout[o];
#pragma unroll
    for (int cgi = 0; cgi < 8; cgi++)
        y += Yp[((size_t)cgi * 32 + o) * 1024 + n];
    float s  = g_pst[b * 8]     + g_pst[b * 8 + 2] + g_pst[b * 8 + 4] + g_pst[b * 8 + 6];
    float s2 = g_pst[b * 8 + 1] + g_pst[b * 8 + 3] + g_pst[b * 8 + 5] + g_pst[b * 8 + 7];
    float mean = s * (1.f / 32768.f);
    float var  = s2 * (1.f / 32768.f) - mean * mean;
    float rstd = rsqrtf(var + EPSGN);
    out[idx] = (y - mean) * rstd * gamma[o] + beta[o];
}

// ============================================================
extern "C" void kernel_launch(void* const* d_in, const int* in_sizes, int n_in,
                              void* d_out, int out_size) {
    (void)in_sizes; (void)n_in; (void)out_size;
    const float* image = (const float*)d_in[0];
    const float* w_qkv = (const float*)d_in[1];
    const float* b_qkv = (const float*)d_in[2];
    const float* w_out = (const float*)d_in[3];
    const float* b_out = (const float*)d_in[4];
    const float* gamma = (const float*)d_in[5];
    const float* beta  = (const float*)d_in[6];
    float* out = (float*)d_out;

    cudaFuncSetAttribute(gemm_mma_kernel,
                         cudaFuncAttributeMaxDynamicSharedMemorySize, GEMM_SMEM);

    qkv_kernel<<<dim3(8, 192, 4), 256>>>(image, w_qkv, b_qkv);        // 1
    ksm_q_kernel<<<dim3(32, 16, 2), 1024>>>();                        // 2
    gemm_mma_kernel<<<dim3(8, 4, 16), 512, GEMM_SMEM>>>(0);           // 3
    gemm_mma_kernel<<<dim3(8, 4, 16), 512, GEMM_SMEM>>>(1);           // 4 (profiled)
    proj_kernel<<<dim3(16, 4, 8), 256>>>(w_out);                      // 5
    stats_kernel<<<16, 1024>>>(b_out);                                // 6
    gn_kernel<<<512, 256>>>(b_out, gamma, beta, out);                 // 7
}

// round 17
// speedup vs baseline: 2.3648x; 1.0251x over previous
#include <cuda_runtime.h>
#include <cuda_fp16.h>
#include <math.h>
#include <stdint.h>

// ---------------- problem constants ----------------
#define NB    4
#define NC    32
#define NSP   1024
#define ND    1024
#define NBH   16
#define SCALE 0.17677669529663687f   // 1/sqrt(32)
#define EPSGN 1e-5f
#define LOG2E 1.4426950408889634f

// ---------------- scratch (device globals; allocation-free) ----------------
__device__ float g_Yp [NB * 8 * NC * NSP];    // proj partials [b][cg][o][n]
__device__ float g_pst[NB * 4 * 2];           // per-(b,og) partial {sum, sumsq}

#define HFN (NBH * ND * NSP / 8)
// natural f16 [z][d][n]:
__device__ uint4 g_QH4[HFN];   // q pre-softmax f16
__device__ uint4 g_KH4[HFN];   // k pre-softmax f16
__device__ uint4 g_Xh4[HFN];   // attention out [z][e][n] f16
// TILE-PACKED + PRE-SWIZZLED f16 (blocks of 8192B = 128 rows x 64B):
__device__ uint4 g_Vf4[HFN];   // v  [e][n]
__device__ uint4 g_Kf4[HFN];   // 256*k-softmax [d][n]
__device__ uint4 g_Qf4[HFN];   // 256*q-softmax^T [n][d]
__device__ uint4 g_Cf4[HFN];   // ctx^T [e][d]

// ---------------- small helpers ----------------
__device__ __forceinline__ uint32_t smem_u32(const void* p) {
    uint32_t a;
    asm("{ .reg .u64 t; cvta.to.shared.u64 t, %1; cvt.u32.u64 %0, t; }" : "=r"(a) : "l"(p));
    return a;
}
__device__ __forceinline__ unsigned packh2(float a, float b) {
    __half2 p = __floats2half2_rn(a, b);
    return *reinterpret_cast<unsigned*>(&p);
}
// polynomial exp2 on the FMA pipe (rel err ~4e-5)
__device__ __forceinline__ float pexp2(float t) {
    t = fmaxf(t, -120.f);
    int i = __float2int_rn(t);
    float f = t - (float)i;
    float p = fmaf(f, 0.0096181f, 0.0555041f);
    p = fmaf(f, p, 0.2402265f);
    p = fmaf(f, p, 0.6931472f);
    p = fmaf(f, p, 1.0f);
    return p * __int_as_float((i + 127) << 23);
}
// byte offset of element (row, k) of matrix z in packed-swizzled layout
__device__ __forceinline__ size_t pkoff(int z, int row, int k) {
    size_t blk = (size_t)(z * 8 + (row >> 7)) * 32 + (k >> 5);
    int r = row & 127, kk = k & 31;
    return blk * 8192 +
           (uint32_t)(r * 64 + ((((kk >> 3) + (r >> 1)) & 3) << 4) + (kk & 7) * 2);
}
__device__ __forceinline__ uint32_t swzoff(int R, int ch) {
    return (uint32_t)(R * 64 + (((ch + (R >> 1)) & 3) << 4));
}
__device__ __forceinline__ void mbar_init(uint32_t a, uint32_t cnt) {
    asm volatile("mbarrier.init.shared.b64 [%0], %1;" :: "r"(a), "r"(cnt) : "memory");
}
__device__ __forceinline__ void mbar_expect_tx(uint32_t a, uint32_t tx) {
    asm volatile("mbarrier.arrive.expect_tx.shared.b64 _, [%0], %1;"
                 :: "r"(a), "r"(tx) : "memory");
}
__device__ __forceinline__ void mbar_arrive(uint32_t a) {
    asm volatile("mbarrier.arrive.shared.b64 _, [%0];" :: "r"(a) : "memory");
}
__device__ __forceinline__ void mbar_wait(uint32_t a, uint32_t phase) {
    asm volatile(
        "{\n\t.reg .pred P;\n"
        "W%=:\n\t"
        "mbarrier.try_wait.parity.shared::cta.b64 P, [%0], %1;\n\t"
        "@!P bra W%=;\n\t}"
        :: "r"(a), "r"(phase) : "memory");
}
__device__ __forceinline__ void mbar_wait_acq(uint32_t a, uint32_t phase) {
    asm volatile(
        "{\n\t.reg .pred P;\n"
        "W%=:\n\t"
        "mbarrier.try_wait.parity.acquire.cta.shared::cta.b64 P, [%0], %1;\n\t"
        "@!P bra W%=;\n\t}"
        :: "r"(a), "r"(phase) : "memory");
}
__device__ __forceinline__ void bulkcp(uint32_t sdst, const void* gsrc,
                                       uint32_t bytes, uint32_t mb) {
    asm volatile(
        "cp.async.bulk.shared::cta.global.mbarrier::complete_tx::bytes [%0], [%1], %2, [%3];"
        :: "r"(sdst), "l"(gsrc), "r"(bytes), "r"(mb) : "memory");
}
__device__ __forceinline__ void ldsm4(unsigned* r, uint32_t addr) {
    asm volatile("ldmatrix.sync.aligned.m8n8.x4.shared.b16 {%0,%1,%2,%3}, [%4];"
                 : "=r"(r[0]), "=r"(r[1]), "=r"(r[2]), "=r"(r[3]) : "r"(addr));
}
__device__ __forceinline__ void mma16816(float* c, const unsigned* a, const unsigned* b) {
    asm volatile(
        "mma.sync.aligned.m16n8k16.row.col.f32.f16.f16.f32 "
        "{%0,%1,%2,%3}, {%4,%5,%6,%7}, {%8,%9}, {%0,%1,%2,%3};"
        : "+f"(c[0]), "+f"(c[1]), "+f"(c[2]), "+f"(c[3])
        : "r"(a[0]), "r"(a[1]), "r"(a[2]), "r"(a[3]), "r"(b[0]), "r"(b[1]));
}

// ============================================================
// Kernel 1: QKV projection. q,k -> f16 natural [d][n]; v -> f16 packed.
// ============================================================
__global__ __launch_bounds__(256) void qkv_kernel(const float* __restrict__ img,
                                                  const float* __restrict__ w,
                                                  const float* __restrict__ bias) {
    __shared__ float xs[32][128];
    __shared__ float ws[64][32];
    __shared__ float bs[64];

    const int b  = blockIdx.z;
    const int o0 = blockIdx.y * 64;
    const int n0 = blockIdx.x * 128;
    const int t  = threadIdx.x;

#pragma unroll
    for (int i = 0; i < 4; i++) {
        int idx = t + 256 * i;
        int c = idx >> 5, c4 = (idx & 31) << 2;
        *(float4*)&xs[c][c4] = *(const float4*)&img[((size_t)b * 32 + c) * 1024 + n0 + c4];
    }
#pragma unroll
    for (int i = 0; i < 2; i++) {
        int idx = t + 256 * i;
        int o = idx >> 3, c4 = (idx & 7) << 2;
        *(float4*)&ws[o][c4] = *(const float4*)&w[(size_t)(o0 + o) * 32 + c4];
    }
    if (t < 64) bs[t] = bias[o0 + t];
    __syncthreads();

    const int tx = t & 31;
    const int oy = t >> 5;

    float acc[8][4];
#pragma unroll
    for (int r = 0; r < 8; r++) {
        float bv = bs[8 * oy + r];
#pragma unroll
        for (int i = 0; i < 4; i++) acc[r][i] = bv;
    }
#pragma unroll
    for (int c = 0; c < 32; c++) {
        float4 x = *(const float4*)&xs[c][4 * tx];
#pragma unroll
        for (int r = 0; r < 8; r++) {
            float wv = ws[8 * oy + r][c];
            acc[r][0] += wv * x.x; acc[r][1] += wv * x.y;
            acc[r][2] += wv * x.z; acc[r][3] += wv * x.w;
        }
    }

    const int nglob = n0 + 4 * tx;
#pragma unroll
    for (int r = 0; r < 8; r++) {
        int o     = o0 + 8 * oy + r;
        int which = o >> 12;
        int oc    = o & 4095;
        int h     = oc & 3;
        int cch   = oc >> 2;
        int zz    = b * 4 + h;
        uint2 hv;
        hv.x = packh2(acc[r][0], acc[r][1]);
        hv.y = packh2(acc[r][2], acc[r][3]);
        if (which == 2) {
            *(uint2*)((char*)g_Vf4 + pkoff(zz, cch, nglob)) = hv;
        } else {
            __half* dst = (which == 0) ? (__half*)g_QH4 : (__half*)g_KH4;
            *(uint2*)&dst[((size_t)zz << 20) + (size_t)cch * 1024 + nglob] = hv;
        }
    }
}

// ============================================================
// Kernel 2 (fused dual-role), dual-pipe exp (MUFU + FMA poly):
// z-slice 0 -> k softmax over n (x256, f16 packed [d][n]);
// z-slice 1 -> q: denominator + softmax-apply (x256) + transpose -> qT[n][d].
// grid (32, 16, 2), block 1024.
// ============================================================
__global__ __launch_bounds__(1024) void ksm_q_kernel() {
    const int z = blockIdx.y;
    if (blockIdx.z == 0) {
        const int lane = threadIdx.x & 31;
        const int w    = threadIdx.x >> 5;
        const int d    = blockIdx.x * 32 + w;
        const __half2* src =
            (const __half2*)((const __half*)g_KH4 + ((size_t)z << 20) + (size_t)d * 1024);

        float2 vals[16];
        float m = -3.402823466e38f;
#pragma unroll
        for (int j = 0; j < 16; j++) {
            __half2 h = src[j * 32 + lane];
            vals[j] = __half22float2(h);
            m = fmaxf(m, fmaxf(vals[j].x, vals[j].y));
        }
#pragma unroll
        for (int o = 16; o; o >>= 1) m = fmaxf(m, __shfl_xor_sync(0xffffffffu, m, o));
        float s = 0.f;
#pragma unroll
        for (int j = 0; j < 16; j++) {
            vals[j].x = __expf(vals[j].x - m);
            vals[j].y = pexp2((vals[j].y - m) * LOG2E);
            s += vals[j].x + vals[j].y;
        }
#pragma unroll
        for (int o = 16; o; o >>= 1) s += __shfl_xor_sync(0xffffffffu, s, o);
        float inv = 256.f / s;

        char* KfB = (char*)g_Kf4;
#pragma unroll
        for (int j = 0; j < 16; j++) {
            unsigned u = packh2(vals[j].x * inv, vals[j].y * inv);
            *(unsigned*)(KfB + pkoff(z, d, j * 64 + 2 * lane)) = u;
        }
    } else {
        __shared__ float red[32][32];
        __shared__ float rinv[32];
        const int nl = threadIdx.x & 31;
        const int dg = threadIdx.x >> 5;
        const int n  = blockIdx.x * 32 + nl;
        const __half* src = (const __half*)g_QH4 + ((size_t)z << 20) + n;

        float vals[32];
        float s = 0.f;
#pragma unroll
        for (int j = 0; j < 32; j += 2) {
            float x0 = __half2float(src[(size_t)(dg * 32 + j) * 1024]);
            float x1 = __half2float(src[(size_t)(dg * 32 + j + 1) * 1024]);
            vals[j]     = __expf(x0);
            vals[j + 1] = pexp2(x1 * LOG2E);
            s += vals[j] + vals[j + 1];
        }
        red[dg][nl] = s;
        __syncthreads();
        if (dg == 0) {
            float tot = 0.f;
#pragma unroll
            for (int r = 0; r < 32; r++) tot += red[r][nl];
            rinv[nl] = 256.f / tot;
        }
        __syncthreads();
        float inv = rinv[nl];

        char* QfB = (char*)g_Qf4;
#pragma unroll
        for (int g = 0; g < 4; g++) {
            uint4 u;
            u.x = packh2(vals[g * 8 + 0] * inv, vals[g * 8 + 1] * inv);
            u.y = packh2(vals[g * 8 + 2] * inv, vals[g * 8 + 3] * inv);
            u.z = packh2(vals[g * 8 + 4] * inv, vals[g * 8 + 5] * inv);
            u.w = packh2(vals[g * 8 + 6] * inv, vals[g * 8 + 7] * inv);
            *(uint4*)(QfB + pkoff(z, n, dg * 32 + g * 8)) = u;
        }
    }
}

// ============================================================
// Kernel 3: single-pass f16 TN GEMM, bulk-TMA + mma.sync,
// full/empty mbarrier ring + SOFTWARE-PIPELINED FRAGMENTS:
// steady state  [ldsm set1(kt) | mma set0(kt)]
//               [wait full(kt+1), ldsm set0(kt+1) | arrive empty(kt), mma set1(kt)]
// 8 warps (warp tile 64x64), CTA 256x128, K chunk 32, NSTAGE=4 x 24KB.
// grid (8 nt, 4 mt, 16 z), block 256.
// ============================================================
#define STAGE_BYTES 24576
#define NSTAGE 4
#define GEMM_SMEM (NSTAGE * STAGE_BYTES + 128)

__global__ __launch_bounds__(256, 1) void gemm_mma_kernel(int stage) {
    extern __shared__ char smem[];
    const uint32_t sbase  = smem_u32(smem);
    const uint32_t mfull  = sbase + NSTAGE * STAGE_BYTES;
    const uint32_t mempty = mfull + 32;
    const int t    = threadIdx.x;
    const int lane = t & 31;
    const int wid  = t >> 5;

    const char *A, *B;
    if (stage == 0) { A = (const char*)g_Vf4; B = (const char*)g_Kf4; }
    else            { A = (const char*)g_Cf4; B = (const char*)g_Qf4; }
    const int z  = blockIdx.z;
    const int mt = blockIdx.y;
    const int nt = blockIdx.x;
    const char* gA0 = A + (size_t)(z * 8 + 2 * mt)     * 32 * 8192;
    const char* gA1 = A + (size_t)(z * 8 + 2 * mt + 1) * 32 * 8192;
    const char* gB  = B + (size_t)(z * 8 + nt)         * 32 * 8192;

    if (t == 0) {
#pragma unroll
        for (int s = 0; s < NSTAGE; s++) {
            mbar_init(mfull  + 8 * s, 1);
            mbar_init(mempty + 8 * s, 8);
        }
        asm volatile("fence.proxy.async.shared::cta;" ::: "memory");
    }
    __syncthreads();

    auto issue = [&](int j) {
        const int st = j & (NSTAGE - 1);
        const uint32_t mb = mfull + 8 * st;
        const uint32_t sb = sbase + st * STAGE_BYTES;
        mbar_expect_tx(mb, STAGE_BYTES);
        bulkcp(sb,         gA0 + (size_t)j * 8192, 8192, mb);
        bulkcp(sb + 8192,  gA1 + (size_t)j * 8192, 8192, mb);
        bulkcp(sb + 16384, gB  + (size_t)j * 8192, 8192, mb);
    };
    if (t == 0) { issue(0); issue(1); issue(2); }

    // warp tile 64x64: wm = wid&3 (m), wn = wid>>2 (n)
    const int wm = wid & 3;
    const int wn = wid >> 2;
    const int aRloc = (wm & 1) * 64 + (lane & 15);
    const int aHalf = wm >> 1;
    const int aHi   = lane >> 4;
    const int bR    = wn * 64 + (lane & 7) + ((lane >> 4) << 3);
    const int bHi   = (lane >> 3) & 1;

    float acc[4][8][4];
#pragma unroll
    for (int i = 0; i < 4; i++)
#pragma unroll
        for (int j = 0; j < 8; j++)
#pragma unroll
            for (int p = 0; p < 4; p++) acc[i][j][p] = 0.f;

    unsigned a0[4][4], b0[4][4], a1[4][4], b1[4][4];

    // prologue: wait stage 0, load set0 (k16 #0)
    mbar_wait_acq(mfull, 0);
    {
        const uint32_t sb = sbase;
        const uint32_t ab = sb + aHalf * 8192;
        const uint32_t bb = sb + 16384;
#pragma unroll
        for (int np = 0; np < 4; np++) ldsm4(b0[np], bb + swzoff(bR + np * 16, bHi));
#pragma unroll
        for (int mb = 0; mb < 4; mb++) ldsm4(a0[mb], ab + swzoff(aRloc + mb * 16, aHi));
    }

#pragma unroll 1
    for (int kt = 0; kt < 32; kt++) {
        const uint32_t sb = sbase + (kt & 3) * STAGE_BYTES;
        const uint32_t ab = sb + aHalf * 8192;
        const uint32_t bb = sb + 16384;

        // load set1 (k16 #1 of current stage)
#pragma unroll
        for (int np = 0; np < 4; np++) ldsm4(b1[np], bb + swzoff(bR + np * 16, 2 + bHi));
#pragma unroll
        for (int mb = 0; mb < 4; mb++) ldsm4(a1[mb], ab + swzoff(aRloc + mb * 16, 2 + aHi));

        // mma set0 (overlaps set1 loads)
#pragma unroll
        for (int mb = 0; mb < 4; mb++)
#pragma unroll
            for (int nb = 0; nb < 8; nb++)
                mma16816(acc[mb][nb], a0[mb], &b0[nb >> 1][(nb & 1) * 2]);

        if (kt < 31) {
            // wait next stage, preload its set0 (k16 #0)
            mbar_wait_acq(mfull + 8 * ((kt + 1) & 3), ((kt + 1) >> 2) & 1);
            const uint32_t sbn = sbase + ((kt + 1) & 3) * STAGE_BYTES;
            const uint32_t abn = sbn + aHalf * 8192;
            const uint32_t bbn = sbn + 16384;
#pragma unroll
            for (int np = 0; np < 4; np++) ldsm4(b0[np], bbn + swzoff(bR + np * 16, bHi));
#pragma unroll
            for (int mb = 0; mb < 4; mb++) ldsm4(a0[mb], abn + swzoff(aRloc + mb * 16, aHi));
        }
        // all reads of current stage issued (set1 this iter, set0 in prior iter)
        if (lane == 0) mbar_arrive(mempty + 8 * (kt & 3));

        // mma set1 (overlaps next-stage set0 loads)
#pragma unroll
        for (int mb = 0; mb < 4; mb++)
#pragma unroll
            for (int nb = 0; nb < 8; nb++)
                mma16816(acc[mb][nb], a1[mb], &b1[nb >> 1][(nb & 1) * 2]);

        // producer refill
        if (t == 0 && kt + 3 < 32) {
            int j = kt + 3;
            if (j >= NSTAGE) mbar_wait(mempty + 8 * (j & 3), ((j >> 2) + 1) & 1);
            issue(j);
        }
    }

    // ---- epilogue
    const int g  = lane >> 2;
    const int tt = lane & 3;
    const int mw = mt * 256 + wm * 64;
    const int nw = nt * 128 + wn * 64;

    if (stage == 0) {
        char* Cf = (char*)g_Cf4;
        const float sc = 1.f / 256.f;
#pragma unroll
        for (int mb = 0; mb < 4; mb++)
#pragma unroll
            for (int nb = 0; nb < 8; nb++) {
                const float* a = acc[mb][nb];
                int m = mw + mb * 16 + g;
                int k = nw + nb * 8 + 2 * tt;
                *(unsigned*)(Cf + pkoff(z, m,     k)) = packh2(a[0] * sc, a[1] * sc);
                *(unsigned*)(Cf + pkoff(z, m + 8, k)) = packh2(a[2] * sc, a[3] * sc);
            }
    } else {
        __half* Xh = (__half*)g_Xh4;
        const float sc = SCALE / 256.f;
        const size_t zoff = (size_t)z << 20;
#pragma unroll
        for (int mb = 0; mb < 4; mb++)
#pragma unroll
            for (int nb = 0; nb < 8; nb++) {
                const float* a = acc[mb][nb];
                size_t base = zoff + (size_t)(mw + mb * 16 + g) * 1024 + nw + nb * 8 + 2 * tt;
                *(unsigned*)&Xh[base]            = packh2(a[0] * sc, a[1] * sc);
                *(unsigned*)&Xh[base + 8 * 1024] = packh2(a[2] * sc, a[3] * sc);
            }
    }
}

// ============================================================
// Kernel 4: output projection PARTIALS, half2-vectorized X reads.
// grid (16 nt, 4 b, 8 cg), block 256 = 32 half2-lanes (64 n) x 8 og.
// ============================================================
__global__ __launch_bounds__(256) void proj_kernel(const float* __restrict__ wout) {
    __shared__ float ws[32][64];
    const int b   = blockIdx.y;
    const int cg  = blockIdx.z;
    const int nn  = blockIdx.x * 32 + (threadIdx.x & 31);  // half2 index
    const int og  = threadIdx.x >> 5;
    const __half2* X2 = (const __half2*)((const __half*)g_Xh4 + ((size_t)b << 22));

    float2 acc[4];
#pragma unroll
    for (int j = 0; j < 4; j++) acc[j] = make_float2(0.f, 0.f);

    for (int c0 = cg * 512; c0 < cg * 512 + 512; c0 += 64) {
        __syncthreads();
#pragma unroll
        for (int i = 0; i < 2; i++) {
            int idx = threadIdx.x + 256 * i;
            int o = idx >> 4, c4 = (idx & 15) << 2;
            *(float4*)&ws[o][c4] = *(const float4*)&wout[(size_t)o * 4096 + c0 + c4];
        }
        __syncthreads();
#pragma unroll 16
        for (int cl = 0; cl < 64; cl++) {
            float2 x = __half22float2(X2[(size_t)(c0 + cl) * 512 + nn]);
#pragma unroll
            for (int j = 0; j < 4; j++) {
                float w = ws[og * 4 + j][cl];
                acc[j].x += w * x.x;
                acc[j].y += w * x.y;
            }
        }
    }
#pragma unroll
    for (int j = 0; j < 4; j++)
        *(float2*)&g_Yp[(((size_t)b * 8 + cg) * 32 + og * 4 + j) * 1024 + 2 * nn] = acc[j];
}

// ============================================================
// Kernel 5: stats — per-(b,og) {sum, sumsq} of y = bias + sum_cg Yp.
// grid (16): b = bx>>2, og = bx&3 (8 o each). block 1024 (one n per thread).
// ============================================================
__global__ __launch_bounds__(1024) void stats_kernel(const float* __restrict__ bout) {
    __shared__ float ss[32], ss2[32];
    const int b  = blockIdx.x >> 2;
    const int og = blockIdx.x & 3;
    const int t  = threadIdx.x;
    const float* Yp = g_Yp + (size_t)b * 8 * 32 * 1024;

    float s = 0.f, s2 = 0.f;
#pragma unroll
    for (int oo = 0; oo < 8; oo++) {
        int o = og * 8 + oo;
        float y = bout[o];
#pragma unroll
        for (int cgi = 0; cgi < 8; cgi++)
            y += Yp[((size_t)cgi * 32 + o) * 1024 + t];
        s += y; s2 += y * y;
    }
#pragma unroll
    for (int o = 16; o; o >>= 1) {
        s  += __shfl_xor_sync(0xffffffffu, s, o);
        s2 += __shfl_xor_sync(0xffffffffu, s2, o);
    }
    if ((t & 31) == 0) { ss[t >> 5] = s; ss2[t >> 5] = s2; }
    __syncthreads();
    if (t < 32) {
        s = ss[t]; s2 = ss2[t];
#pragma unroll
        for (int o = 16; o; o >>= 1) {
            s  += __shfl_xor_sync(0xffffffffu, s, o);
            s2 += __shfl_xor_sync(0xffffffffu, s2, o);
        }
        if (t == 0) {
            g_pst[(b * 4 + og) * 2]     = s;
            g_pst[(b * 4 + og) * 2 + 1] = s2;
        }
    }
}

// ============================================================
// Kernel 6: GroupNorm finalize -> d_out (recomputes y from Yp).
// ============================================================
__global__ void gn_kernel(const float* __restrict__ bout,
                          const float* __restrict__ gamma,
                          const float* __restrict__ beta,
                          float* __restrict__ out) {
    int idx = blockIdx.x * 256 + threadIdx.x;
    int b = idx >> 15;
    int o = (idx >> 10) & 31;
    int n = idx & 1023;
    const float* Yp = g_Yp + (size_t)b * 8 * 32 * 1024;
    float y = bout[o];
#pragma unroll
    for (int cgi = 0; cgi < 8; cgi++)
        y += Yp[((size_t)cgi * 32 + o) * 1024 + n];
    float s  = g_pst[b * 8]     + g_pst[b * 8 + 2] + g_pst[b * 8 + 4] + g_pst[b * 8 + 6];
    float s2 = g_pst[b * 8 + 1] + g_pst[b * 8 + 3] + g_pst[b * 8 + 5] + g_pst[b * 8 + 7];
    float mean = s * (1.f / 32768.f);
    float var  = s2 * (1.f / 32768.f) - mean * mean;
    float rstd = rsqrtf(var + EPSGN);
    out[idx] = (y - mean) * rstd * gamma[o] + beta[o];
}

// ============================================================
extern "C" void kernel_launch(void* const* d_in, const int* in_sizes, int n_in,
                              void* d_out, int out_size) {
    (void)in_sizes; (void)n_in; (void)out_size;
    const float* image = (const float*)d_in[0];
    const float* w_qkv = (const float*)d_in[1];
    const float* b_qkv = (const float*)d_in[2];
    const float* w_out = (const float*)d_in[3];
    const float* b_out = (const float*)d_in[4];
    const float* gamma = (const float*)d_in[5];
    const float* beta  = (const float*)d_in[6];
    float* out = (float*)d_out;

    cudaFuncSetAttribute(gemm_mma_kernel,
                         cudaFuncAttributeMaxDynamicSharedMemorySize, GEMM_SMEM);

    qkv_kernel<<<dim3(8, 192, 4), 256>>>(image, w_qkv, b_qkv);        // 1
    ksm_q_kernel<<<dim3(32, 16, 2), 1024>>>();                        // 2
    gemm_mma_kernel<<<dim3(8, 4, 16), 256, GEMM_SMEM>>>(0);           // 3
    gemm_mma_kernel<<<dim3(8, 4, 16), 256, GEMM_SMEM>>>(1);           // 4 (profiled)
    proj_kernel<<<dim3(16, 4, 8), 256>>>(w_out);                      // 5
    stats_kernel<<<16, 1024>>>(b_out);                                // 6
    gn_kernel<<<512, 256>>>(b_out, gamma, beta, out);                 // 7
}